// round 1
// baseline (speedup 1.0000x reference)
#include <cuda_runtime.h>
#include <math.h>

// Problem constants
constexpr int Bz  = 4;
constexpr int SQ  = 4096;
constexpr int SKV = 1024;
constexpr int QD  = 1024;
constexpr int CD  = 768;
constexpr int H   = 16;
constexpr int Dh  = 64;
constexpr int ID  = 1024;          // H * Dh
constexpr float ATT_SCALE = 0.125f; // 64^-0.5

// Scratch (alloc-free rule: __device__ globals)
__device__ float g_Q [(size_t)Bz * SQ  * ID];
__device__ float g_K [(size_t)Bz * SKV * ID];
__device__ float g_V [(size_t)Bz * SKV * ID];
__device__ float g_AO[(size_t)Bz * SQ  * ID];

// ---------------------------------------------------------------------------
// Classic SGEMM: C[M,N] = A[M,K] @ B[K,N] (+bias), 128x128 block, BK=8,
// 256 threads, 8x8 register tile per thread. All dims divide tiles exactly.
// ---------------------------------------------------------------------------
template <bool BIAS>
__global__ __launch_bounds__(256) void sgemm128(
    const float* __restrict__ A, const float* __restrict__ Bm,
    const float* __restrict__ bias, float* __restrict__ C,
    int M, int N, int K)
{
    __shared__ float As[8][128];
    __shared__ float Bs[8][128];

    const int tid = threadIdx.x;
    const int bm = blockIdx.y, bn = blockIdx.x;
    const float* Ab = A + (size_t)bm * 128 * K;
    const float* Bb = Bm + (size_t)bn * 128;

    const int ar = tid >> 1, ac = (tid & 1) * 4;   // A tile: 128 rows x 8 cols
    const int br = tid >> 5, bc = (tid & 31) * 4;  // B tile: 8 rows x 128 cols
    const int ty = tid >> 4, tx = tid & 15;

    float acc[8][8];
#pragma unroll
    for (int i = 0; i < 8; i++)
#pragma unroll
        for (int j = 0; j < 8; j++) acc[i][j] = 0.f;

    for (int k0 = 0; k0 < K; k0 += 8) {
        __syncthreads();
        float4 av = *(const float4*)(Ab + (size_t)ar * K + k0 + ac);
        float4 bv = *(const float4*)(Bb + (size_t)(k0 + br) * N + bc);
        As[ac + 0][ar] = av.x;
        As[ac + 1][ar] = av.y;
        As[ac + 2][ar] = av.z;
        As[ac + 3][ar] = av.w;
        *(float4*)&Bs[br][bc] = bv;
        __syncthreads();

#pragma unroll
        for (int k = 0; k < 8; k++) {
            float a[8], b[8];
            *(float4*)(a)     = *(const float4*)&As[k][ty * 8];
            *(float4*)(a + 4) = *(const float4*)&As[k][ty * 8 + 4];
            *(float4*)(b)     = *(const float4*)&Bs[k][tx * 8];
            *(float4*)(b + 4) = *(const float4*)&Bs[k][tx * 8 + 4];
#pragma unroll
            for (int i = 0; i < 8; i++)
#pragma unroll
                for (int j = 0; j < 8; j++)
                    acc[i][j] = fmaf(a[i], b[j], acc[i][j]);
        }
    }

    const size_t row0 = (size_t)bm * 128 + ty * 8;
    const int col0 = bn * 128 + tx * 8;
    float bv[8];
#pragma unroll
    for (int j = 0; j < 8; j++) bv[j] = BIAS ? bias[col0 + j] : 0.f;

#pragma unroll
    for (int i = 0; i < 8; i++) {
        float* cp = C + (row0 + i) * (size_t)N + col0;
        float4 o0, o1;
        o0.x = acc[i][0] + bv[0]; o0.y = acc[i][1] + bv[1];
        o0.z = acc[i][2] + bv[2]; o0.w = acc[i][3] + bv[3];
        o1.x = acc[i][4] + bv[4]; o1.y = acc[i][5] + bv[5];
        o1.z = acc[i][6] + bv[6]; o1.w = acc[i][7] + bv[7];
        *(float4*)(cp)     = o0;
        *(float4*)(cp + 4) = o1;
    }
}

// ---------------------------------------------------------------------------
// Flash attention, fp32. One block per (b, h, 64-row Q tile).
// 256 threads; 4x4 micro-tiles for QK^T and PV; online softmax.
// Q/K/V are stored as (b, s, h*64+d) row-major [*, 1024] matrices.
// ---------------------------------------------------------------------------
__global__ __launch_bounds__(256) void flash64(
    const float* __restrict__ Q, const float* __restrict__ Kc,
    const float* __restrict__ Vc, float* __restrict__ O)
{
    extern __shared__ float sm[];
    constexpr int LD = 65; // pad: keeps worst LDS conflicts at 2-way
    float* sQ = sm;
    float* sK = sQ + 64 * LD;
    float* sV = sK + 64 * LD;
    float* sS = sV + 64 * LD;
    float* sM = sS + 64 * LD;
    float* sL = sM + 64;
    float* sF = sL + 64;

    const int tid = threadIdx.x;
    const int b = blockIdx.y >> 4, h = blockIdx.y & 15;
    const int q0 = blockIdx.x * 64;

    const float* Qb = Q  + ((size_t)(b * SQ + q0)) * ID + h * Dh;
    const float* Kb = Kc + ((size_t)b * SKV) * ID + h * Dh;
    const float* Vb = Vc + ((size_t)b * SKV) * ID + h * Dh;

    // Load 64x64 Q tile
    {
        const int r = tid >> 2, c = (tid & 3) * 16;
#pragma unroll
        for (int i = 0; i < 16; i += 4) {
            float4 v = *(const float4*)(Qb + (size_t)r * ID + c + i);
            sQ[r * LD + c + i + 0] = v.x;
            sQ[r * LD + c + i + 1] = v.y;
            sQ[r * LD + c + i + 2] = v.z;
            sQ[r * LD + c + i + 3] = v.w;
        }
    }
    if (tid < 64) { sM[tid] = -1e30f; sL[tid] = 0.f; }

    const int ty = tid >> 4, tx = tid & 15;
    float o[4][4];
#pragma unroll
    for (int i = 0; i < 4; i++)
#pragma unroll
        for (int j = 0; j < 4; j++) o[i][j] = 0.f;

    for (int jt = 0; jt < SKV / 64; jt++) {
        __syncthreads(); // prior iter done with sK/sV/sS; Q-load visible on iter 0
        {
            const int r = tid >> 2, c = (tid & 3) * 16;
            const float* kp = Kb + (size_t)(jt * 64 + r) * ID + c;
            const float* vp = Vb + (size_t)(jt * 64 + r) * ID + c;
#pragma unroll
            for (int i = 0; i < 16; i += 4) {
                float4 kv = *(const float4*)(kp + i);
                float4 vv = *(const float4*)(vp + i);
                sK[r * LD + c + i + 0] = kv.x; sK[r * LD + c + i + 1] = kv.y;
                sK[r * LD + c + i + 2] = kv.z; sK[r * LD + c + i + 3] = kv.w;
                sV[r * LD + c + i + 0] = vv.x; sV[r * LD + c + i + 1] = vv.y;
                sV[r * LD + c + i + 2] = vv.z; sV[r * LD + c + i + 3] = vv.w;
            }
        }
        __syncthreads();

        // S = (Q tile) @ (K tile)^T
        float s[4][4];
#pragma unroll
        for (int i = 0; i < 4; i++)
#pragma unroll
            for (int j = 0; j < 4; j++) s[i][j] = 0.f;

#pragma unroll 8
        for (int d = 0; d < 64; d++) {
            float a0 = sQ[(ty * 4 + 0) * LD + d];
            float a1 = sQ[(ty * 4 + 1) * LD + d];
            float a2 = sQ[(ty * 4 + 2) * LD + d];
            float a3 = sQ[(ty * 4 + 3) * LD + d];
            float b0 = sK[(tx * 4 + 0) * LD + d];
            float b1 = sK[(tx * 4 + 1) * LD + d];
            float b2 = sK[(tx * 4 + 2) * LD + d];
            float b3 = sK[(tx * 4 + 3) * LD + d];
            s[0][0] = fmaf(a0, b0, s[0][0]); s[0][1] = fmaf(a0, b1, s[0][1]);
            s[0][2] = fmaf(a0, b2, s[0][2]); s[0][3] = fmaf(a0, b3, s[0][3]);
            s[1][0] = fmaf(a1, b0, s[1][0]); s[1][1] = fmaf(a1, b1, s[1][1]);
            s[1][2] = fmaf(a1, b2, s[1][2]); s[1][3] = fmaf(a1, b3, s[1][3]);
            s[2][0] = fmaf(a2, b0, s[2][0]); s[2][1] = fmaf(a2, b1, s[2][1]);
            s[2][2] = fmaf(a2, b2, s[2][2]); s[2][3] = fmaf(a2, b3, s[2][3]);
            s[3][0] = fmaf(a3, b0, s[3][0]); s[3][1] = fmaf(a3, b1, s[3][1]);
            s[3][2] = fmaf(a3, b2, s[3][2]); s[3][3] = fmaf(a3, b3, s[3][3]);
        }
#pragma unroll
        for (int i = 0; i < 4; i++)
#pragma unroll
            for (int j = 0; j < 4; j++)
                sS[(ty * 4 + i) * LD + tx * 4 + j] = s[i][j] * ATT_SCALE;
        __syncthreads();

        // Online softmax row update (one thread per row)
        if (tid < 64) {
            float mo = sM[tid];
            float mx = mo;
            float* row = sS + tid * LD;
#pragma unroll 16
            for (int c2 = 0; c2 < 64; c2++) mx = fmaxf(mx, row[c2]);
            float sum = 0.f;
#pragma unroll 16
            for (int c2 = 0; c2 < 64; c2++) {
                float p = __expf(row[c2] - mx);
                row[c2] = p;
                sum += p;
            }
            float f = __expf(mo - mx);
            sF[tid] = f;
            sM[tid] = mx;
            sL[tid] = sL[tid] * f + sum;
        }
        __syncthreads();

        // Rescale accumulators and add P @ V
        float f0 = sF[ty * 4 + 0], f1 = sF[ty * 4 + 1];
        float f2 = sF[ty * 4 + 2], f3 = sF[ty * 4 + 3];
#pragma unroll
        for (int j = 0; j < 4; j++) {
            o[0][j] *= f0; o[1][j] *= f1; o[2][j] *= f2; o[3][j] *= f3;
        }
#pragma unroll 8
        for (int jj = 0; jj < 64; jj++) {
            float p0 = sS[(ty * 4 + 0) * LD + jj];
            float p1 = sS[(ty * 4 + 1) * LD + jj];
            float p2 = sS[(ty * 4 + 2) * LD + jj];
            float p3 = sS[(ty * 4 + 3) * LD + jj];
            float v0 = sV[jj * LD + tx * 4 + 0];
            float v1 = sV[jj * LD + tx * 4 + 1];
            float v2 = sV[jj * LD + tx * 4 + 2];
            float v3 = sV[jj * LD + tx * 4 + 3];
            o[0][0] = fmaf(p0, v0, o[0][0]); o[0][1] = fmaf(p0, v1, o[0][1]);
            o[0][2] = fmaf(p0, v2, o[0][2]); o[0][3] = fmaf(p0, v3, o[0][3]);
            o[1][0] = fmaf(p1, v0, o[1][0]); o[1][1] = fmaf(p1, v1, o[1][1]);
            o[1][2] = fmaf(p1, v2, o[1][2]); o[1][3] = fmaf(p1, v3, o[1][3]);
            o[2][0] = fmaf(p2, v0, o[2][0]); o[2][1] = fmaf(p2, v1, o[2][1]);
            o[2][2] = fmaf(p2, v2, o[2][2]); o[2][3] = fmaf(p2, v3, o[2][3]);
            o[3][0] = fmaf(p3, v0, o[3][0]); o[3][1] = fmaf(p3, v1, o[3][1]);
            o[3][2] = fmaf(p3, v2, o[3][2]); o[3][3] = fmaf(p3, v3, o[3][3]);
        }
    }

    // Final normalize and write (sL last written before a __syncthreads in loop)
    float inv0 = 1.f / sL[ty * 4 + 0];
    float inv1 = 1.f / sL[ty * 4 + 1];
    float inv2 = 1.f / sL[ty * 4 + 2];
    float inv3 = 1.f / sL[ty * 4 + 3];
    float invs[4] = {inv0, inv1, inv2, inv3};
    float* Ob = O + ((size_t)(b * SQ + q0)) * ID + h * Dh;
#pragma unroll
    for (int i = 0; i < 4; i++) {
        float4 w;
        w.x = o[i][0] * invs[i];
        w.y = o[i][1] * invs[i];
        w.z = o[i][2] * invs[i];
        w.w = o[i][3] * invs[i];
        *(float4*)(Ob + (size_t)(ty * 4 + i) * ID + tx * 4) = w;
    }
}

// ---------------------------------------------------------------------------
// Launch
// ---------------------------------------------------------------------------
extern "C" void kernel_launch(void* const* d_in, const int* in_sizes, int n_in,
                              void* d_out, int out_size)
{
    const float* x   = (const float*)d_in[0];
    const float* ctx = (const float*)d_in[1];
    const float* Wq  = (const float*)d_in[2];
    const float* Wk  = (const float*)d_in[3];
    const float* Wv  = (const float*)d_in[4];
    const float* Wo  = (const float*)d_in[5];
    const float* bo  = (const float*)d_in[6];
    float* out = (float*)d_out;

    float *qp, *kp, *vp, *aop;
    cudaGetSymbolAddress((void**)&qp,  g_Q);
    cudaGetSymbolAddress((void**)&kp,  g_K);
    cudaGetSymbolAddress((void**)&vp,  g_V);
    cudaGetSymbolAddress((void**)&aop, g_AO);

    dim3 blk(256);

    // Projections
    sgemm128<false><<<dim3(ID / 128, (Bz * SQ) / 128),  blk>>>(x,   Wq, nullptr, qp, Bz * SQ,  ID, QD);
    sgemm128<false><<<dim3(ID / 128, (Bz * SKV) / 128), blk>>>(ctx, Wk, nullptr, kp, Bz * SKV, ID, CD);
    sgemm128<false><<<dim3(ID / 128, (Bz * SKV) / 128), blk>>>(ctx, Wv, nullptr, vp, Bz * SKV, ID, CD);

    // Attention
    const int smem = (4 * 64 * 65 + 3 * 64) * (int)sizeof(float); // 67,328 B
    cudaFuncSetAttribute(flash64, cudaFuncAttributeMaxDynamicSharedMemorySize, smem);
    flash64<<<dim3(SQ / 64, Bz * H), blk, smem>>>(qp, kp, vp, aop);

    // Output projection (+bias)
    sgemm128<true><<<dim3(QD / 128, (Bz * SQ) / 128), blk>>>(aop, Wo, bo, out, Bz * SQ, QD, ID);
}

// round 3
// speedup vs baseline: 1.2960x; 1.2960x over previous
#include <cuda_runtime.h>
#include <cuda_bf16.h>
#include <math.h>
#include <stdint.h>

// ---------------------------------------------------------------------------
// Problem constants
// ---------------------------------------------------------------------------
constexpr int Bz  = 4;
constexpr int SQ  = 4096;
constexpr int SKV = 1024;
constexpr int QD  = 1024;
constexpr int CD  = 768;
constexpr int H   = 16;
constexpr int Dh  = 64;
constexpr int ID  = 1024;
constexpr float ATT_SCALE = 0.125f;

constexpr size_t NX  = (size_t)Bz * SQ  * QD;
constexpr size_t NCX = (size_t)Bz * SKV * CD;
constexpr size_t NQe = (size_t)Bz * SQ  * ID;
constexpr size_t NKV = (size_t)Bz * SKV * ID;

// ---------------------------------------------------------------------------
// Scratch (__device__ globals; alloc-free rule)
// ---------------------------------------------------------------------------
__device__ float g_Q [NQe];
__device__ float g_K [NKV];
__device__ float g_V [NKV];
__device__ float g_AO[NQe];

__device__ __nv_bfloat16 g_xh[NX],  g_xl[NX];
__device__ __nv_bfloat16 g_ch[NCX], g_cl[NCX];
__device__ __nv_bfloat16 g_aoh[NQe], g_aol[NQe];
// Transposed weights, stored [N,K] K-major
__device__ __nv_bfloat16 g_wqh[(size_t)ID*QD], g_wql[(size_t)ID*QD];
__device__ __nv_bfloat16 g_wkh[(size_t)ID*CD], g_wkl[(size_t)ID*CD];
__device__ __nv_bfloat16 g_wvh[(size_t)ID*CD], g_wvl[(size_t)ID*CD];
__device__ __nv_bfloat16 g_woh[(size_t)QD*ID], g_wol[(size_t)QD*ID];

// ---------------------------------------------------------------------------
// mma.sync / ldmatrix helpers (plain sm_103-safe PTX, sm_80-era ISA)
// ---------------------------------------------------------------------------
__device__ __forceinline__ uint32_t smem_u32(const void* p) {
    uint32_t a;
    asm("{ .reg .u64 t; cvta.to.shared.u64 t, %1; cvt.u32.u64 %0, t; }"
        : "=r"(a) : "l"(p));
    return a;
}

#define LDSM4(r, addr)                                                        \
    asm volatile("ldmatrix.sync.aligned.m8n8.x4.shared.b16 {%0,%1,%2,%3}, [%4];" \
        : "=r"((r)[0]), "=r"((r)[1]), "=r"((r)[2]), "=r"((r)[3]) : "r"(addr))

#define MMA16816(c, a, b0, b1)                                                \
    asm volatile("mma.sync.aligned.m16n8k16.row.col.f32.bf16.bf16.f32 "       \
        "{%0,%1,%2,%3}, {%4,%5,%6,%7}, {%8,%9}, {%0,%1,%2,%3};"               \
        : "+f"((c)[0]), "+f"((c)[1]), "+f"((c)[2]), "+f"((c)[3])              \
        : "r"((a)[0]), "r"((a)[1]), "r"((a)[2]), "r"((a)[3]),                 \
          "r"(b0), "r"(b1))

// ---------------------------------------------------------------------------
// fp32 -> (hi, lo) bf16 split, elementwise
// ---------------------------------------------------------------------------
__global__ void splitk(const float* __restrict__ s, __nv_bfloat16* __restrict__ hi,
                       __nv_bfloat16* __restrict__ lo, int n4) {
    int i = blockIdx.x * blockDim.x + threadIdx.x;
    if (i >= n4) return;
    float4 v = ((const float4*)s)[i];
    float a[4] = {v.x, v.y, v.z, v.w};
    __nv_bfloat16 h[4], l[4];
#pragma unroll
    for (int j = 0; j < 4; j++) {
        h[j] = __float2bfloat16(a[j]);
        l[j] = __float2bfloat16(a[j] - __bfloat162float(h[j]));
    }
    ((float2*)hi)[i] = *(float2*)h;
    ((float2*)lo)[i] = *(float2*)l;
}

// ---------------------------------------------------------------------------
// W[K,N] fp32 -> WT[N,K] bf16 hi/lo (tiled transpose + split)
// ---------------------------------------------------------------------------
__global__ void tsplit(const float* __restrict__ W, __nv_bfloat16* __restrict__ hiT,
                       __nv_bfloat16* __restrict__ loT, int K, int N) {
    __shared__ float t[32][33];
    int nb = blockIdx.x * 32, kb = blockIdx.y * 32;
    int tx = threadIdx.x, ty = threadIdx.y;
    for (int r = ty; r < 32; r += 8)
        t[r][tx] = W[(size_t)(kb + r) * N + nb + tx];
    __syncthreads();
    for (int r = ty; r < 32; r += 8) {
        float a = t[tx][r];
        __nv_bfloat16 h = __float2bfloat16(a);
        __nv_bfloat16 l = __float2bfloat16(a - __bfloat162float(h));
        hiT[(size_t)(nb + r) * K + kb + tx] = h;
        loT[(size_t)(nb + r) * K + kb + tx] = l;
    }
}

// ---------------------------------------------------------------------------
// Split-bf16 GEMM via mma.sync: C[M,N] = A[M,K] @ W[K,N] (+bias)
//   A as (Ahi, Alo) [M,K]; W as transposed (BThi, BTlo) [N,K] (col-major B).
//   3 accumulation passes: Ahi*Bhi + Alo*Bhi + Ahi*Blo into fp32 accumulators.
//   CTA 128x128, BK=32, 8 warps (2x4), warp tile 64x32, m16n8k16 fragments.
// ---------------------------------------------------------------------------
constexpr int STR = 40;  // smem row stride in bf16 (80 B): conflict-free ldmatrix

template <bool BIAS>
__global__ __launch_bounds__(256) void mm_s(
    const __nv_bfloat16* __restrict__ Ahi, const __nv_bfloat16* __restrict__ Alo,
    const __nv_bfloat16* __restrict__ BThi, const __nv_bfloat16* __restrict__ BTlo,
    const float* __restrict__ bias, float* __restrict__ C,
    int M, int N, int K)
{
    __shared__ __nv_bfloat16 sA[128 * STR];
    __shared__ __nv_bfloat16 sB[128 * STR];

    const int tid  = threadIdx.x;
    const int lane = tid & 31;
    const int wid  = tid >> 5;
    const int wm   = wid & 1;   // 2 m-tiles of 64
    const int wn   = wid >> 1;  // 4 n-tiles of 32
    const int bm = blockIdx.y, bn = blockIdx.x;

    // ldmatrix per-thread addressing
    const int g  = lane >> 3, lr = lane & 7;
    const int aRow  = (g & 1) * 8 + lr;
    const int aKoff = (g >> 1) * 16;        // bytes
    const int bRow  = (g >> 1) * 8 + lr;
    const int bKoff = (g & 1) * 16;         // bytes

    const uint32_t sAu = smem_u32(sA);
    const uint32_t sBu = smem_u32(sB);
    const uint32_t aBase = sAu + (uint32_t)(wm * 64 + aRow) * (STR * 2) + aKoff;
    const uint32_t bBase = sBu + (uint32_t)(wn * 32 + bRow) * (STR * 2) + bKoff;

    float acc[4][4][4];
#pragma unroll
    for (int i = 0; i < 4; i++)
#pragma unroll
        for (int j = 0; j < 4; j++)
#pragma unroll
            for (int q = 0; q < 4; q++) acc[i][j][q] = 0.f;

    const int kc = K / 32;
    const int nchunks = 3 * kc;

    const int u0 = tid, u1 = tid + 256;
    const int r0 = u0 >> 2, c0 = (u0 & 3) * 8;
    const int r1 = u1 >> 2, c1 = (u1 & 3) * 8;

    auto srcA = [&](int c) { return (c / kc == 1) ? Alo : Ahi; };
    auto srcB = [&](int c) { return (c / kc == 2) ? BTlo : BThi; };

    // Prefetch chunk 0
    uint4 pa0, pa1, pb0, pb1;
    {
        const __nv_bfloat16* Ag = srcA(0) + (size_t)(bm * 128) * K;
        const __nv_bfloat16* Bg = srcB(0) + (size_t)(bn * 128) * K;
        pa0 = *(const uint4*)(Ag + (size_t)r0 * K + c0);
        pa1 = *(const uint4*)(Ag + (size_t)r1 * K + c1);
        pb0 = *(const uint4*)(Bg + (size_t)r0 * K + c0);
        pb1 = *(const uint4*)(Bg + (size_t)r1 * K + c1);
    }

    for (int c = 0; c < nchunks; ++c) {
        __syncthreads();
        *(uint4*)(sA + r0 * STR + c0) = pa0;
        *(uint4*)(sA + r1 * STR + c1) = pa1;
        *(uint4*)(sB + r0 * STR + c0) = pb0;
        *(uint4*)(sB + r1 * STR + c1) = pb1;
        __syncthreads();

        if (c + 1 < nchunks) {
            const int cn = c + 1;
            const int k0 = (cn % kc) * 32;
            const __nv_bfloat16* Ag = srcA(cn) + (size_t)(bm * 128) * K + k0;
            const __nv_bfloat16* Bg = srcB(cn) + (size_t)(bn * 128) * K + k0;
            pa0 = *(const uint4*)(Ag + (size_t)r0 * K + c0);
            pa1 = *(const uint4*)(Ag + (size_t)r1 * K + c1);
            pb0 = *(const uint4*)(Bg + (size_t)r0 * K + c0);
            pb1 = *(const uint4*)(Bg + (size_t)r1 * K + c1);
        }

#pragma unroll
        for (int k16 = 0; k16 < 2; k16++) {
            uint32_t a[4][4];
#pragma unroll
            for (int mi = 0; mi < 4; mi++)
                LDSM4(a[mi], aBase + (uint32_t)(mi * 16) * (STR * 2) + k16 * 32);
#pragma unroll
            for (int j4 = 0; j4 < 2; j4++) {
                uint32_t q[4];
                LDSM4(q, bBase + (uint32_t)(j4 * 16) * (STR * 2) + k16 * 32);
#pragma unroll
                for (int mi = 0; mi < 4; mi++) {
                    MMA16816(acc[mi][2 * j4 + 0], a[mi], q[0], q[1]);
                    MMA16816(acc[mi][2 * j4 + 1], a[mi], q[2], q[3]);
                }
            }
        }
    }

    // Epilogue
    const int tr = lane >> 2, tc = (lane & 3) * 2;
#pragma unroll
    for (int mi = 0; mi < 4; mi++) {
#pragma unroll
        for (int nj = 0; nj < 4; nj++) {
            const int row = bm * 128 + wm * 64 + mi * 16 + tr;
            const int col = bn * 128 + wn * 32 + nj * 8 + tc;
            float b0 = BIAS ? bias[col] : 0.f;
            float b1 = BIAS ? bias[col + 1] : 0.f;
            float2 v0 = {acc[mi][nj][0] + b0, acc[mi][nj][1] + b1};
            float2 v1 = {acc[mi][nj][2] + b0, acc[mi][nj][3] + b1};
            *(float2*)(C + (size_t)row * N + col)       = v0;
            *(float2*)(C + (size_t)(row + 8) * N + col) = v1;
        }
    }
}

// ---------------------------------------------------------------------------
// Flash attention, fp32 (unchanged from Round 1)
// ---------------------------------------------------------------------------
__global__ __launch_bounds__(256) void flash64(
    const float* __restrict__ Q, const float* __restrict__ Kc,
    const float* __restrict__ Vc, float* __restrict__ O)
{
    extern __shared__ float sm[];
    constexpr int LD = 65;
    float* sQ = sm;
    float* sK = sQ + 64 * LD;
    float* sV = sK + 64 * LD;
    float* sS = sV + 64 * LD;
    float* sM = sS + 64 * LD;
    float* sL = sM + 64;
    float* sF = sL + 64;

    const int tid = threadIdx.x;
    const int b = blockIdx.y >> 4, h = blockIdx.y & 15;
    const int q0 = blockIdx.x * 64;

    const float* Qb = Q  + ((size_t)(b * SQ + q0)) * ID + h * Dh;
    const float* Kb = Kc + ((size_t)b * SKV) * ID + h * Dh;
    const float* Vb = Vc + ((size_t)b * SKV) * ID + h * Dh;

    {
        const int r = tid >> 2, c = (tid & 3) * 16;
#pragma unroll
        for (int i = 0; i < 16; i += 4) {
            float4 v = *(const float4*)(Qb + (size_t)r * ID + c + i);
            sQ[r * LD + c + i + 0] = v.x; sQ[r * LD + c + i + 1] = v.y;
            sQ[r * LD + c + i + 2] = v.z; sQ[r * LD + c + i + 3] = v.w;
        }
    }
    if (tid < 64) { sM[tid] = -1e30f; sL[tid] = 0.f; }

    const int ty = tid >> 4, tx = tid & 15;
    float o[4][4];
#pragma unroll
    for (int i = 0; i < 4; i++)
#pragma unroll
        for (int j = 0; j < 4; j++) o[i][j] = 0.f;

    for (int jt = 0; jt < SKV / 64; jt++) {
        __syncthreads();
        {
            const int r = tid >> 2, c = (tid & 3) * 16;
            const float* kp = Kb + (size_t)(jt * 64 + r) * ID + c;
            const float* vp = Vb + (size_t)(jt * 64 + r) * ID + c;
#pragma unroll
            for (int i = 0; i < 16; i += 4) {
                float4 kv = *(const float4*)(kp + i);
                float4 vv = *(const float4*)(vp + i);
                sK[r * LD + c + i + 0] = kv.x; sK[r * LD + c + i + 1] = kv.y;
                sK[r * LD + c + i + 2] = kv.z; sK[r * LD + c + i + 3] = kv.w;
                sV[r * LD + c + i + 0] = vv.x; sV[r * LD + c + i + 1] = vv.y;
                sV[r * LD + c + i + 2] = vv.z; sV[r * LD + c + i + 3] = vv.w;
            }
        }
        __syncthreads();

        float s[4][4];
#pragma unroll
        for (int i = 0; i < 4; i++)
#pragma unroll
            for (int j = 0; j < 4; j++) s[i][j] = 0.f;

#pragma unroll 8
        for (int d = 0; d < 64; d++) {
            float a0 = sQ[(ty * 4 + 0) * LD + d];
            float a1 = sQ[(ty * 4 + 1) * LD + d];
            float a2 = sQ[(ty * 4 + 2) * LD + d];
            float a3 = sQ[(ty * 4 + 3) * LD + d];
            float b0 = sK[(tx * 4 + 0) * LD + d];
            float b1 = sK[(tx * 4 + 1) * LD + d];
            float b2 = sK[(tx * 4 + 2) * LD + d];
            float b3 = sK[(tx * 4 + 3) * LD + d];
            s[0][0] = fmaf(a0, b0, s[0][0]); s[0][1] = fmaf(a0, b1, s[0][1]);
            s[0][2] = fmaf(a0, b2, s[0][2]); s[0][3] = fmaf(a0, b3, s[0][3]);
            s[1][0] = fmaf(a1, b0, s[1][0]); s[1][1] = fmaf(a1, b1, s[1][1]);
            s[1][2] = fmaf(a1, b2, s[1][2]); s[1][3] = fmaf(a1, b3, s[1][3]);
            s[2][0] = fmaf(a2, b0, s[2][0]); s[2][1] = fmaf(a2, b1, s[2][1]);
            s[2][2] = fmaf(a2, b2, s[2][2]); s[2][3] = fmaf(a2, b3, s[2][3]);
            s[3][0] = fmaf(a3, b0, s[3][0]); s[3][1] = fmaf(a3, b1, s[3][1]);
            s[3][2] = fmaf(a3, b2, s[3][2]); s[3][3] = fmaf(a3, b3, s[3][3]);
        }
#pragma unroll
        for (int i = 0; i < 4; i++)
#pragma unroll
            for (int j = 0; j < 4; j++)
                sS[(ty * 4 + i) * LD + tx * 4 + j] = s[i][j] * ATT_SCALE;
        __syncthreads();

        if (tid < 64) {
            float mo = sM[tid];
            float mx = mo;
            float* row = sS + tid * LD;
#pragma unroll 16
            for (int c2 = 0; c2 < 64; c2++) mx = fmaxf(mx, row[c2]);
            float sum = 0.f;
#pragma unroll 16
            for (int c2 = 0; c2 < 64; c2++) {
                float p = __expf(row[c2] - mx);
                row[c2] = p;
                sum += p;
            }
            float f = __expf(mo - mx);
            sF[tid] = f;
            sM[tid] = mx;
            sL[tid] = sL[tid] * f + sum;
        }
        __syncthreads();

        float f0 = sF[ty * 4 + 0], f1 = sF[ty * 4 + 1];
        float f2 = sF[ty * 4 + 2], f3 = sF[ty * 4 + 3];
#pragma unroll
        for (int j = 0; j < 4; j++) {
            o[0][j] *= f0; o[1][j] *= f1; o[2][j] *= f2; o[3][j] *= f3;
        }
#pragma unroll 8
        for (int jj = 0; jj < 64; jj++) {
            float p0 = sS[(ty * 4 + 0) * LD + jj];
            float p1 = sS[(ty * 4 + 1) * LD + jj];
            float p2 = sS[(ty * 4 + 2) * LD + jj];
            float p3 = sS[(ty * 4 + 3) * LD + jj];
            float v0 = sV[jj * LD + tx * 4 + 0];
            float v1 = sV[jj * LD + tx * 4 + 1];
            float v2 = sV[jj * LD + tx * 4 + 2];
            float v3 = sV[jj * LD + tx * 4 + 3];
            o[0][0] = fmaf(p0, v0, o[0][0]); o[0][1] = fmaf(p0, v1, o[0][1]);
            o[0][2] = fmaf(p0, v2, o[0][2]); o[0][3] = fmaf(p0, v3, o[0][3]);
            o[1][0] = fmaf(p1, v0, o[1][0]); o[1][1] = fmaf(p1, v1, o[1][1]);
            o[1][2] = fmaf(p1, v2, o[1][2]); o[1][3] = fmaf(p1, v3, o[1][3]);
            o[2][0] = fmaf(p2, v0, o[2][0]); o[2][1] = fmaf(p2, v1, o[2][1]);
            o[2][2] = fmaf(p2, v2, o[2][2]); o[2][3] = fmaf(p2, v3, o[2][3]);
            o[3][0] = fmaf(p3, v0, o[3][0]); o[3][1] = fmaf(p3, v1, o[3][1]);
            o[3][2] = fmaf(p3, v2, o[3][2]); o[3][3] = fmaf(p3, v3, o[3][3]);
        }
    }

    float invs[4] = {1.f / sL[ty * 4 + 0], 1.f / sL[ty * 4 + 1],
                     1.f / sL[ty * 4 + 2], 1.f / sL[ty * 4 + 3]};
    float* Ob = O + ((size_t)(b * SQ + q0)) * ID + h * Dh;
#pragma unroll
    for (int i = 0; i < 4; i++) {
        float4 w;
        w.x = o[i][0] * invs[i]; w.y = o[i][1] * invs[i];
        w.z = o[i][2] * invs[i]; w.w = o[i][3] * invs[i];
        *(float4*)(Ob + (size_t)(ty * 4 + i) * ID + tx * 4) = w;
    }
}

// ---------------------------------------------------------------------------
// Launch
// ---------------------------------------------------------------------------
extern "C" void kernel_launch(void* const* d_in, const int* in_sizes, int n_in,
                              void* d_out, int out_size)
{
    const float* x   = (const float*)d_in[0];
    const float* ctx = (const float*)d_in[1];
    const float* Wq  = (const float*)d_in[2];
    const float* Wk  = (const float*)d_in[3];
    const float* Wv  = (const float*)d_in[4];
    const float* Wo  = (const float*)d_in[5];
    const float* bo  = (const float*)d_in[6];
    float* out = (float*)d_out;

    float *qp, *kp, *vp, *aop;
    cudaGetSymbolAddress((void**)&qp,  g_Q);
    cudaGetSymbolAddress((void**)&kp,  g_K);
    cudaGetSymbolAddress((void**)&vp,  g_V);
    cudaGetSymbolAddress((void**)&aop, g_AO);
    __nv_bfloat16 *xh, *xl, *ch, *cl, *aoh, *aol;
    __nv_bfloat16 *wqh, *wql, *wkh, *wkl, *wvh, *wvl, *woh, *wol;
    cudaGetSymbolAddress((void**)&xh,  g_xh);  cudaGetSymbolAddress((void**)&xl,  g_xl);
    cudaGetSymbolAddress((void**)&ch,  g_ch);  cudaGetSymbolAddress((void**)&cl,  g_cl);
    cudaGetSymbolAddress((void**)&aoh, g_aoh); cudaGetSymbolAddress((void**)&aol, g_aol);
    cudaGetSymbolAddress((void**)&wqh, g_wqh); cudaGetSymbolAddress((void**)&wql, g_wql);
    cudaGetSymbolAddress((void**)&wkh, g_wkh); cudaGetSymbolAddress((void**)&wkl, g_wkl);
    cudaGetSymbolAddress((void**)&wvh, g_wvh); cudaGetSymbolAddress((void**)&wvl, g_wvl);
    cudaGetSymbolAddress((void**)&woh, g_woh); cudaGetSymbolAddress((void**)&wol, g_wol);

    const int fsmem = (4 * 64 * 65 + 3 * 64) * (int)sizeof(float);
    cudaFuncSetAttribute(flash64, cudaFuncAttributeMaxDynamicSharedMemorySize, fsmem);

    // Input conversions
    splitk<<<(int)(NX  / 4 / 256), 256>>>(x,   xh, xl, (int)(NX  / 4));
    splitk<<<(int)(NCX / 4 / 256), 256>>>(ctx, ch, cl, (int)(NCX / 4));
    tsplit<<<dim3(ID / 32, QD / 32), dim3(32, 8)>>>(Wq, wqh, wql, QD, ID);
    tsplit<<<dim3(ID / 32, CD / 32), dim3(32, 8)>>>(Wk, wkh, wkl, CD, ID);
    tsplit<<<dim3(ID / 32, CD / 32), dim3(32, 8)>>>(Wv, wvh, wvl, CD, ID);
    tsplit<<<dim3(QD / 32, ID / 32), dim3(32, 8)>>>(Wo, woh, wol, ID, QD);

    // Projections (mma.sync split-bf16)
    mm_s<false><<<dim3(ID / 128, (Bz * SQ)  / 128), 256>>>(xh, xl, wqh, wql, nullptr, qp, Bz * SQ,  ID, QD);
    mm_s<false><<<dim3(ID / 128, (Bz * SKV) / 128), 256>>>(ch, cl, wkh, wkl, nullptr, kp, Bz * SKV, ID, CD);
    mm_s<false><<<dim3(ID / 128, (Bz * SKV) / 128), 256>>>(ch, cl, wvh, wvl, nullptr, vp, Bz * SKV, ID, CD);

    // Attention (fp32 flash)
    flash64<<<dim3(SQ / 64, Bz * H), 256, fsmem>>>(qp, kp, vp, aop);

    // Output projection
    splitk<<<(int)(NQe / 4 / 256), 256>>>(aop, aoh, aol, (int)(NQe / 4));
    mm_s<true><<<dim3(QD / 128, (Bz * SQ) / 128), 256>>>(aoh, aol, woh, wol, bo, out, Bz * SQ, QD, ID);
}

// round 4
// speedup vs baseline: 2.9936x; 2.3099x over previous
#include <cuda_runtime.h>
#include <cuda_bf16.h>
#include <cuda_fp16.h>
#include <math.h>
#include <stdint.h>

// ---------------------------------------------------------------------------
// Problem constants
// ---------------------------------------------------------------------------
constexpr int Bz  = 4;
constexpr int SQ  = 4096;
constexpr int SKV = 1024;
constexpr int QD  = 1024;
constexpr int CD  = 768;
constexpr int H   = 16;
constexpr int Dh  = 64;
constexpr int ID  = 1024;
constexpr float ATT_SCALE = 0.125f;

constexpr size_t NX  = (size_t)Bz * SQ  * QD;
constexpr size_t NCX = (size_t)Bz * SKV * CD;
constexpr size_t NQe = (size_t)Bz * SQ  * ID;
constexpr size_t NKV = (size_t)Bz * SKV * ID;

// ---------------------------------------------------------------------------
// Scratch (__device__ globals; alloc-free rule)
// ---------------------------------------------------------------------------
__device__ __half g_qh[NQe], g_ql[NQe];
__device__ __half g_kh[NKV];
__device__ __half g_vh[NKV], g_vl[NKV];
__device__ __nv_bfloat16 g_aoh[NQe], g_aol[NQe];

__device__ __nv_bfloat16 g_xh[NX],  g_xl[NX];
__device__ __nv_bfloat16 g_ch[NCX], g_cl[NCX];
// Transposed weights, stored [N,K] K-major
__device__ __nv_bfloat16 g_wqh[(size_t)ID*QD], g_wql[(size_t)ID*QD];
__device__ __nv_bfloat16 g_wkh[(size_t)ID*CD], g_wkl[(size_t)ID*CD];
__device__ __nv_bfloat16 g_wvh[(size_t)ID*CD], g_wvl[(size_t)ID*CD];
__device__ __nv_bfloat16 g_woh[(size_t)QD*ID], g_wol[(size_t)QD*ID];

// ---------------------------------------------------------------------------
// PTX helpers (plain sm_103-safe: sm_80-era mma.sync / ldmatrix / cp.async)
// ---------------------------------------------------------------------------
__device__ __forceinline__ uint32_t smem_u32(const void* p) {
    uint32_t a;
    asm("{ .reg .u64 t; cvta.to.shared.u64 t, %1; cvt.u32.u64 %0, t; }"
        : "=r"(a) : "l"(p));
    return a;
}

#define LDSM4(r, addr)                                                        \
    asm volatile("ldmatrix.sync.aligned.m8n8.x4.shared.b16 {%0,%1,%2,%3}, [%4];" \
        : "=r"((r)[0]), "=r"((r)[1]), "=r"((r)[2]), "=r"((r)[3]) : "r"(addr))

#define LDSM4T(r, addr)                                                       \
    asm volatile("ldmatrix.sync.aligned.m8n8.x4.trans.shared.b16 {%0,%1,%2,%3}, [%4];" \
        : "=r"((r)[0]), "=r"((r)[1]), "=r"((r)[2]), "=r"((r)[3]) : "r"(addr))

#define MMA_BF16(c, a, b0, b1)                                                \
    asm volatile("mma.sync.aligned.m16n8k16.row.col.f32.bf16.bf16.f32 "       \
        "{%0,%1,%2,%3}, {%4,%5,%6,%7}, {%8,%9}, {%0,%1,%2,%3};"               \
        : "+f"((c)[0]), "+f"((c)[1]), "+f"((c)[2]), "+f"((c)[3])              \
        : "r"((a)[0]), "r"((a)[1]), "r"((a)[2]), "r"((a)[3]), "r"(b0), "r"(b1))

#define MMA_F16(c, a, b0, b1)                                                 \
    asm volatile("mma.sync.aligned.m16n8k16.row.col.f32.f16.f16.f32 "         \
        "{%0,%1,%2,%3}, {%4,%5,%6,%7}, {%8,%9}, {%0,%1,%2,%3};"               \
        : "+f"((c)[0]), "+f"((c)[1]), "+f"((c)[2]), "+f"((c)[3])              \
        : "r"((a)[0]), "r"((a)[1]), "r"((a)[2]), "r"((a)[3]), "r"(b0), "r"(b1))

#define CP_ASYNC16(daddr, gptr)                                               \
    asm volatile("cp.async.cg.shared.global [%0], [%1], 16;"                  \
        :: "r"(daddr), "l"(gptr))
#define CP_COMMIT() asm volatile("cp.async.commit_group;" ::: "memory")

__device__ __forceinline__ uint32_t pack2h(float a, float b) {
    __half2 h = __floats2half2_rn(a, b);
    return *reinterpret_cast<uint32_t*>(&h);
}

// ---------------------------------------------------------------------------
// fp32 -> (hi, lo) bf16 split, elementwise
// ---------------------------------------------------------------------------
__global__ void splitk(const float* __restrict__ s, __nv_bfloat16* __restrict__ hi,
                       __nv_bfloat16* __restrict__ lo, int n4) {
    int i = blockIdx.x * blockDim.x + threadIdx.x;
    if (i >= n4) return;
    float4 v = ((const float4*)s)[i];
    float a[4] = {v.x, v.y, v.z, v.w};
    __nv_bfloat16 h[4], l[4];
#pragma unroll
    for (int j = 0; j < 4; j++) {
        h[j] = __float2bfloat16(a[j]);
        l[j] = __float2bfloat16(a[j] - __bfloat162float(h[j]));
    }
    ((float2*)hi)[i] = *(float2*)h;
    ((float2*)lo)[i] = *(float2*)l;
}

// ---------------------------------------------------------------------------
// W[K,N] fp32 -> WT[N,K] bf16 hi/lo (tiled transpose + split)
// ---------------------------------------------------------------------------
__global__ void tsplit(const float* __restrict__ W, __nv_bfloat16* __restrict__ hiT,
                       __nv_bfloat16* __restrict__ loT, int K, int N) {
    __shared__ float t[32][33];
    int nb = blockIdx.x * 32, kb = blockIdx.y * 32;
    int tx = threadIdx.x, ty = threadIdx.y;
    for (int r = ty; r < 32; r += 8)
        t[r][tx] = W[(size_t)(kb + r) * N + nb + tx];
    __syncthreads();
    for (int r = ty; r < 32; r += 8) {
        float a = t[tx][r];
        __nv_bfloat16 h = __float2bfloat16(a);
        __nv_bfloat16 l = __float2bfloat16(a - __bfloat162float(h));
        hiT[(size_t)(nb + r) * K + kb + tx] = h;
        loT[(size_t)(nb + r) * K + kb + tx] = l;
    }
}

// ---------------------------------------------------------------------------
// Split-bf16 GEMM via mma.sync: C[M,N] = A[M,K] @ W[K,N]
//   OM=0: fp32 out + bias (O1=float*)
//   OM=1: fp16 hi/lo outs (O1,O2=__half*)
//   OM=2: fp16 single out (O1=__half*)
// ---------------------------------------------------------------------------
constexpr int STR = 40;

template <int OM>
__global__ __launch_bounds__(256) void mm_s(
    const __nv_bfloat16* __restrict__ Ahi, const __nv_bfloat16* __restrict__ Alo,
    const __nv_bfloat16* __restrict__ BThi, const __nv_bfloat16* __restrict__ BTlo,
    const float* __restrict__ bias, void* __restrict__ O1, void* __restrict__ O2,
    int M, int N, int K)
{
    __shared__ __nv_bfloat16 sA[128 * STR];
    __shared__ __nv_bfloat16 sB[128 * STR];

    const int tid  = threadIdx.x;
    const int lane = tid & 31;
    const int wid  = tid >> 5;
    const int wm   = wid & 1;
    const int wn   = wid >> 1;
    const int bm = blockIdx.y, bn = blockIdx.x;

    const int g  = lane >> 3, lr = lane & 7;
    const int aRow  = (g & 1) * 8 + lr;
    const int aKoff = (g >> 1) * 16;
    const int bRow  = (g >> 1) * 8 + lr;
    const int bKoff = (g & 1) * 16;

    const uint32_t sAu = smem_u32(sA);
    const uint32_t sBu = smem_u32(sB);
    const uint32_t aBase = sAu + (uint32_t)(wm * 64 + aRow) * (STR * 2) + aKoff;
    const uint32_t bBase = sBu + (uint32_t)(wn * 32 + bRow) * (STR * 2) + bKoff;

    float acc[4][4][4];
#pragma unroll
    for (int i = 0; i < 4; i++)
#pragma unroll
        for (int j = 0; j < 4; j++)
#pragma unroll
            for (int q = 0; q < 4; q++) acc[i][j][q] = 0.f;

    const int kc = K / 32;
    const int nchunks = 3 * kc;

    const int u0 = tid, u1 = tid + 256;
    const int r0 = u0 >> 2, c0 = (u0 & 3) * 8;
    const int r1 = u1 >> 2, c1 = (u1 & 3) * 8;

    auto srcA = [&](int c) { return (c / kc == 1) ? Alo : Ahi; };
    auto srcB = [&](int c) { return (c / kc == 2) ? BTlo : BThi; };

    uint4 pa0, pa1, pb0, pb1;
    {
        const __nv_bfloat16* Ag = srcA(0) + (size_t)(bm * 128) * K;
        const __nv_bfloat16* Bg = srcB(0) + (size_t)(bn * 128) * K;
        pa0 = *(const uint4*)(Ag + (size_t)r0 * K + c0);
        pa1 = *(const uint4*)(Ag + (size_t)r1 * K + c1);
        pb0 = *(const uint4*)(Bg + (size_t)r0 * K + c0);
        pb1 = *(const uint4*)(Bg + (size_t)r1 * K + c1);
    }

    for (int c = 0; c < nchunks; ++c) {
        __syncthreads();
        *(uint4*)(sA + r0 * STR + c0) = pa0;
        *(uint4*)(sA + r1 * STR + c1) = pa1;
        *(uint4*)(sB + r0 * STR + c0) = pb0;
        *(uint4*)(sB + r1 * STR + c1) = pb1;
        __syncthreads();

        if (c + 1 < nchunks) {
            const int cn = c + 1;
            const int k0 = (cn % kc) * 32;
            const __nv_bfloat16* Ag = srcA(cn) + (size_t)(bm * 128) * K + k0;
            const __nv_bfloat16* Bg = srcB(cn) + (size_t)(bn * 128) * K + k0;
            pa0 = *(const uint4*)(Ag + (size_t)r0 * K + c0);
            pa1 = *(const uint4*)(Ag + (size_t)r1 * K + c1);
            pb0 = *(const uint4*)(Bg + (size_t)r0 * K + c0);
            pb1 = *(const uint4*)(Bg + (size_t)r1 * K + c1);
        }

#pragma unroll
        for (int k16 = 0; k16 < 2; k16++) {
            uint32_t a[4][4];
#pragma unroll
            for (int mi = 0; mi < 4; mi++)
                LDSM4(a[mi], aBase + (uint32_t)(mi * 16) * (STR * 2) + k16 * 32);
#pragma unroll
            for (int j4 = 0; j4 < 2; j4++) {
                uint32_t q[4];
                LDSM4(q, bBase + (uint32_t)(j4 * 16) * (STR * 2) + k16 * 32);
#pragma unroll
                for (int mi = 0; mi < 4; mi++) {
                    MMA_BF16(acc[mi][2 * j4 + 0], a[mi], q[0], q[1]);
                    MMA_BF16(acc[mi][2 * j4 + 1], a[mi], q[2], q[3]);
                }
            }
        }
    }

    const int tr = lane >> 2, tc = (lane & 3) * 2;
#pragma unroll
    for (int mi = 0; mi < 4; mi++) {
#pragma unroll
        for (int nj = 0; nj < 4; nj++) {
            const int row = bm * 128 + wm * 64 + mi * 16 + tr;
            const int col = bn * 128 + wn * 32 + nj * 8 + tc;
#pragma unroll
            for (int half_ = 0; half_ < 2; half_++) {
                const int rr = row + half_ * 8;
                float x0 = acc[mi][nj][half_ * 2 + 0];
                float x1 = acc[mi][nj][half_ * 2 + 1];
                if (OM == 0) {
                    float* C = (float*)O1;
                    float2 v = {x0 + bias[col], x1 + bias[col + 1]};
                    *(float2*)(C + (size_t)rr * N + col) = v;
                } else if (OM == 1) {
                    __half* Ph = (__half*)O1; __half* Pl = (__half*)O2;
                    __half h0 = __float2half_rn(x0);
                    __half h1 = __float2half_rn(x1);
                    __half l0 = __float2half_rn(x0 - __half2float(h0));
                    __half l1 = __float2half_rn(x1 - __half2float(h1));
                    __half2 vh; vh.x = h0; vh.y = h1;
                    __half2 vl; vl.x = l0; vl.y = l1;
                    *(__half2*)(Ph + (size_t)rr * N + col) = vh;
                    *(__half2*)(Pl + (size_t)rr * N + col) = vl;
                } else {
                    __half* Ph = (__half*)O1;
                    __half2 vh; vh.x = __float2half_rn(x0); vh.y = __float2half_rn(x1);
                    *(__half2*)(Ph + (size_t)rr * N + col) = vh;
                }
            }
        }
    }
}

// ---------------------------------------------------------------------------
// Tensor-core flash attention (fp16 mma, fp32 softmax/accum)
//   CTA: 128 Q rows x full Dh=64; 8 warps x 16 rows; kv tiles of 64.
//   S = (Qh + Ql) @ K^T  (Q fp16-split 2-pass; K fp16)
//   O = P @ (Vh + Vl)    (P fp16; V fp16-split 2-pass)
//   K/V double-buffered via cp.async. Writes AO as bf16 hi/lo.
// ---------------------------------------------------------------------------
constexpr int FP = 72;                       // smem pitch in halfs (144 B)
constexpr int FQ_ELE = 128 * FP;             // per Q array
constexpr int FT_ELE = 64 * FP;              // per K/V tile
constexpr int FBUF_ELE = 3 * FT_ELE;         // K + Vh + Vl
constexpr int FSMEM = (2 * FQ_ELE + 2 * FBUF_ELE) * 2;  // bytes = 92160

__global__ __launch_bounds__(256) void flash_mma(
    const __half* __restrict__ Qh, const __half* __restrict__ Ql,
    const __half* __restrict__ Kh,
    const __half* __restrict__ Vh, const __half* __restrict__ Vl,
    __nv_bfloat16* __restrict__ AOh, __nv_bfloat16* __restrict__ AOl)
{
    extern __shared__ __half fsm[];
    __half* sQh = fsm;
    __half* sQl = sQh + FQ_ELE;
    __half* sBuf = sQl + FQ_ELE;             // 2 x (K | Vh | Vl)

    const int tid  = threadIdx.x;
    const int lane = tid & 31;
    const int w    = tid >> 5;
    const int b  = blockIdx.y >> 4, h = blockIdx.y & 15;
    const size_t bq  = (size_t)b * SQ + blockIdx.x * 128;
    const size_t bkv = (size_t)b * SKV;
    const int hc = h * Dh;

    // ---- load Q tile (128x64) hi/lo to smem ----
    {
        const int r = tid >> 1, c8 = (tid & 1) * 4;  // 128 rows x 8 uint4-cols; 2 cols per thread x 4
#pragma unroll
        for (int i = 0; i < 4; i++) {
            int cc = c8 + (i & 3);
            *(uint4*)(sQh + r * FP + cc * 8) =
                *(const uint4*)(Qh + (bq + r) * ID + hc + cc * 8);
            *(uint4*)(sQl + r * FP + cc * 8) =
                *(const uint4*)(Ql + (bq + r) * ID + hc + cc * 8);
        }
    }

    // ---- cp.async issue helper for tile jt into buffer bi ----
    auto issue_tile = [&](int jt, int bi) {
        uint32_t kb  = smem_u32(sBuf + bi * FBUF_ELE);
        uint32_t vhb = kb + FT_ELE * 2;
        uint32_t vlb = vhb + FT_ELE * 2;
        const size_t grow = (bkv + jt * 64) * ID + hc;
#pragma unroll
        for (int i = 0; i < 2; i++) {
            int idx = tid + i * 256;
            int r = idx >> 3, c8 = idx & 7;
            uint32_t so = (uint32_t)(r * FP + c8 * 8) * 2;
            const __half* gp = Kh + grow + (size_t)r * ID + c8 * 8;
            CP_ASYNC16(kb + so, gp);
        }
#pragma unroll
        for (int i = 0; i < 2; i++) {
            int idx = tid + i * 256;
            int r = idx >> 3, c8 = idx & 7;
            uint32_t so = (uint32_t)(r * FP + c8 * 8) * 2;
            CP_ASYNC16(vhb + so, Vh + grow + (size_t)r * ID + c8 * 8);
            CP_ASYNC16(vlb + so, Vl + grow + (size_t)r * ID + c8 * 8);
        }
        CP_COMMIT();
    };

    issue_tile(0, 0);
    __syncthreads();   // Q smem stores visible

    // ---- load Q fragments (held across whole kv loop) ----
    const int g2 = lane >> 3, lr = lane & 7;
    const int aRow = (g2 & 1) * 8 + lr, aK = (g2 >> 1) * 16;
    uint32_t qhf[4][4], qlf[4][4];
    {
        uint32_t qhB = smem_u32(sQh) + (uint32_t)(w * 16 + aRow) * (FP * 2) + aK;
        uint32_t qlB = smem_u32(sQl) + (uint32_t)(w * 16 + aRow) * (FP * 2) + aK;
#pragma unroll
        for (int kd = 0; kd < 4; kd++) {
            LDSM4(qhf[kd], qhB + kd * 32);
            LDSM4(qlf[kd], qlB + kd * 32);
        }
    }

    const int bRow = (g2 >> 1) * 8 + lr, bK = (g2 & 1) * 16;   // K frags
    const int vRow = (g2 & 1) * 8 + lr, vCol = (g2 >> 1) * 8;  // V trans frags

    float o[8][4];
#pragma unroll
    for (int j = 0; j < 8; j++)
#pragma unroll
        for (int q = 0; q < 4; q++) o[j][q] = 0.f;
    float m0 = -1e30f, m1 = -1e30f, l0 = 0.f, l1 = 0.f;

    constexpr int NT = SKV / 64;  // 16
    for (int jt = 0; jt < NT; jt++) {
        if (jt + 1 < NT) issue_tile(jt + 1, (jt + 1) & 1);
        if (jt == NT - 1) asm volatile("cp.async.wait_group 0;" ::: "memory");
        else              asm volatile("cp.async.wait_group 1;" ::: "memory");
        __syncthreads();

        const int bi = jt & 1;
        const uint32_t kBase  = smem_u32(sBuf + bi * FBUF_ELE) + (uint32_t)bRow * (FP * 2) + bK;
        const uint32_t vhBase = smem_u32(sBuf + bi * FBUF_ELE + FT_ELE) + (uint32_t)vRow * (FP * 2) + vCol * 2;
        const uint32_t vlBase = vhBase + FT_ELE * 2;

        // ---- S = (Qh + Ql) @ K^T ----
        float s[8][4];
#pragma unroll
        for (int j = 0; j < 8; j++)
#pragma unroll
            for (int q = 0; q < 4; q++) s[j][q] = 0.f;

#pragma unroll
        for (int kd = 0; kd < 4; kd++) {
#pragma unroll
            for (int jn = 0; jn < 4; jn++) {
                uint32_t kf[4];
                LDSM4(kf, kBase + (uint32_t)(jn * 16) * (FP * 2) + kd * 32);
                MMA_F16(s[2 * jn + 0], qhf[kd], kf[0], kf[1]);
                MMA_F16(s[2 * jn + 1], qhf[kd], kf[2], kf[3]);
                MMA_F16(s[2 * jn + 0], qlf[kd], kf[0], kf[1]);
                MMA_F16(s[2 * jn + 1], qlf[kd], kf[2], kf[3]);
            }
        }

        // ---- online softmax (rows: lane>>2 and +8) ----
        float mx0 = -1e30f, mx1 = -1e30f;
#pragma unroll
        for (int j = 0; j < 8; j++) {
            s[j][0] *= ATT_SCALE; s[j][1] *= ATT_SCALE;
            s[j][2] *= ATT_SCALE; s[j][3] *= ATT_SCALE;
            mx0 = fmaxf(mx0, fmaxf(s[j][0], s[j][1]));
            mx1 = fmaxf(mx1, fmaxf(s[j][2], s[j][3]));
        }
        mx0 = fmaxf(mx0, __shfl_xor_sync(0xffffffffu, mx0, 1));
        mx0 = fmaxf(mx0, __shfl_xor_sync(0xffffffffu, mx0, 2));
        mx1 = fmaxf(mx1, __shfl_xor_sync(0xffffffffu, mx1, 1));
        mx1 = fmaxf(mx1, __shfl_xor_sync(0xffffffffu, mx1, 2));

        const float m0n = fmaxf(m0, mx0), m1n = fmaxf(m1, mx1);
        const float f0 = __expf(m0 - m0n), f1 = __expf(m1 - m1n);
        float sum0 = 0.f, sum1 = 0.f;
#pragma unroll
        for (int j = 0; j < 8; j++) {
            s[j][0] = __expf(s[j][0] - m0n); s[j][1] = __expf(s[j][1] - m0n);
            s[j][2] = __expf(s[j][2] - m1n); s[j][3] = __expf(s[j][3] - m1n);
            sum0 += s[j][0] + s[j][1];
            sum1 += s[j][2] + s[j][3];
        }
        sum0 += __shfl_xor_sync(0xffffffffu, sum0, 1);
        sum0 += __shfl_xor_sync(0xffffffffu, sum0, 2);
        sum1 += __shfl_xor_sync(0xffffffffu, sum1, 1);
        sum1 += __shfl_xor_sync(0xffffffffu, sum1, 2);
        l0 = l0 * f0 + sum0;
        l1 = l1 * f1 + sum1;
        m0 = m0n; m1 = m1n;

#pragma unroll
        for (int j = 0; j < 8; j++) {
            o[j][0] *= f0; o[j][1] *= f0;
            o[j][2] *= f1; o[j][3] *= f1;
        }

        // ---- P fragments (in-register C->A conversion) ----
        uint32_t pf[4][4];
#pragma unroll
        for (int kd = 0; kd < 4; kd++) {
            pf[kd][0] = pack2h(s[2 * kd + 0][0], s[2 * kd + 0][1]);
            pf[kd][1] = pack2h(s[2 * kd + 0][2], s[2 * kd + 0][3]);
            pf[kd][2] = pack2h(s[2 * kd + 1][0], s[2 * kd + 1][1]);
            pf[kd][3] = pack2h(s[2 * kd + 1][2], s[2 * kd + 1][3]);
        }

        // ---- O += P @ (Vh + Vl) ----
#pragma unroll
        for (int kd = 0; kd < 4; kd++) {
#pragma unroll
            for (int jn = 0; jn < 4; jn++) {
                uint32_t vf[4];
                LDSM4T(vf, vhBase + (uint32_t)(kd * 16) * (FP * 2) + jn * 32);
                MMA_F16(o[2 * jn + 0], pf[kd], vf[0], vf[1]);
                MMA_F16(o[2 * jn + 1], pf[kd], vf[2], vf[3]);
                LDSM4T(vf, vlBase + (uint32_t)(kd * 16) * (FP * 2) + jn * 32);
                MMA_F16(o[2 * jn + 0], pf[kd], vf[0], vf[1]);
                MMA_F16(o[2 * jn + 1], pf[kd], vf[2], vf[3]);
            }
        }
        __syncthreads();   // protect buffer before next issue overwrites
    }

    // ---- epilogue: O/l -> bf16 hi/lo ----
    const float inv0 = 1.f / l0, inv1 = 1.f / l1;
    const int rg = lane >> 2, tc = (lane & 3) * 2;
#pragma unroll
    for (int j = 0; j < 8; j++) {
        const int col = hc + j * 8 + tc;
#pragma unroll
        for (int half_ = 0; half_ < 2; half_++) {
            const size_t row = bq + w * 16 + rg + half_ * 8;
            float x0 = o[j][half_ * 2 + 0] * (half_ ? inv1 : inv0);
            float x1 = o[j][half_ * 2 + 1] * (half_ ? inv1 : inv0);
            __nv_bfloat16 h0 = __float2bfloat16(x0);
            __nv_bfloat16 h1 = __float2bfloat16(x1);
            __nv_bfloat16 e0 = __float2bfloat16(x0 - __bfloat162float(h0));
            __nv_bfloat16 e1 = __float2bfloat16(x1 - __bfloat162float(h1));
            __nv_bfloat162 vh; vh.x = h0; vh.y = h1;
            __nv_bfloat162 vl; vl.x = e0; vl.y = e1;
            *(__nv_bfloat162*)(AOh + row * ID + col) = vh;
            *(__nv_bfloat162*)(AOl + row * ID + col) = vl;
        }
    }
}

// ---------------------------------------------------------------------------
// Launch
// ---------------------------------------------------------------------------
extern "C" void kernel_launch(void* const* d_in, const int* in_sizes, int n_in,
                              void* d_out, int out_size)
{
    const float* x   = (const float*)d_in[0];
    const float* ctx = (const float*)d_in[1];
    const float* Wq  = (const float*)d_in[2];
    const float* Wk  = (const float*)d_in[3];
    const float* Wv  = (const float*)d_in[4];
    const float* Wo  = (const float*)d_in[5];
    const float* bo  = (const float*)d_in[6];
    float* out = (float*)d_out;

    __half *qh, *ql, *kh, *vh, *vl;
    __nv_bfloat16 *aoh, *aol, *xh, *xl, *ch, *cl;
    __nv_bfloat16 *wqh, *wql, *wkh, *wkl, *wvh, *wvl, *woh, *wol;
    cudaGetSymbolAddress((void**)&qh,  g_qh);  cudaGetSymbolAddress((void**)&ql,  g_ql);
    cudaGetSymbolAddress((void**)&kh,  g_kh);
    cudaGetSymbolAddress((void**)&vh,  g_vh);  cudaGetSymbolAddress((void**)&vl,  g_vl);
    cudaGetSymbolAddress((void**)&aoh, g_aoh); cudaGetSymbolAddress((void**)&aol, g_aol);
    cudaGetSymbolAddress((void**)&xh,  g_xh);  cudaGetSymbolAddress((void**)&xl,  g_xl);
    cudaGetSymbolAddress((void**)&ch,  g_ch);  cudaGetSymbolAddress((void**)&cl,  g_cl);
    cudaGetSymbolAddress((void**)&wqh, g_wqh); cudaGetSymbolAddress((void**)&wql, g_wql);
    cudaGetSymbolAddress((void**)&wkh, g_wkh); cudaGetSymbolAddress((void**)&wkl, g_wkl);
    cudaGetSymbolAddress((void**)&wvh, g_wvh); cudaGetSymbolAddress((void**)&wvl, g_wvl);
    cudaGetSymbolAddress((void**)&woh, g_woh); cudaGetSymbolAddress((void**)&wol, g_wol);

    cudaFuncSetAttribute(flash_mma, cudaFuncAttributeMaxDynamicSharedMemorySize, FSMEM);

    // Input conversions
    splitk<<<(int)(NX  / 4 / 256), 256>>>(x,   xh, xl, (int)(NX  / 4));
    splitk<<<(int)(NCX / 4 / 256), 256>>>(ctx, ch, cl, (int)(NCX / 4));
    tsplit<<<dim3(ID / 32, QD / 32), dim3(32, 8)>>>(Wq, wqh, wql, QD, ID);
    tsplit<<<dim3(ID / 32, CD / 32), dim3(32, 8)>>>(Wk, wkh, wkl, CD, ID);
    tsplit<<<dim3(ID / 32, CD / 32), dim3(32, 8)>>>(Wv, wvh, wvl, CD, ID);
    tsplit<<<dim3(QD / 32, ID / 32), dim3(32, 8)>>>(Wo, woh, wol, ID, QD);

    // Projections: Q -> fp16 hi/lo, K -> fp16, V -> fp16 hi/lo
    mm_s<1><<<dim3(ID / 128, (Bz * SQ)  / 128), 256>>>(xh, xl, wqh, wql, nullptr, qh, ql, Bz * SQ,  ID, QD);
    mm_s<2><<<dim3(ID / 128, (Bz * SKV) / 128), 256>>>(ch, cl, wkh, wkl, nullptr, kh, nullptr, Bz * SKV, ID, CD);
    mm_s<1><<<dim3(ID / 128, (Bz * SKV) / 128), 256>>>(ch, cl, wvh, wvl, nullptr, vh, vl, Bz * SKV, ID, CD);

    // Attention (tensor-core flash) -> bf16 hi/lo
    flash_mma<<<dim3(SQ / 128, Bz * H), 256, FSMEM>>>(qh, ql, kh, vh, vl, aoh, aol);

    // Output projection (+bias) -> fp32
    mm_s<0><<<dim3(QD / 128, (Bz * SQ) / 128), 256>>>(aoh, aol, woh, wol, bo, out, nullptr, Bz * SQ, QD, ID);
}

// round 5
// speedup vs baseline: 3.1832x; 1.0633x over previous
#include <cuda_runtime.h>
#include <cuda_bf16.h>
#include <cuda_fp16.h>
#include <math.h>
#include <stdint.h>

// ---------------------------------------------------------------------------
// Problem constants
// ---------------------------------------------------------------------------
constexpr int Bz  = 4;
constexpr int SQ  = 4096;
constexpr int SKV = 1024;
constexpr int QD  = 1024;
constexpr int CD  = 768;
constexpr int H   = 16;
constexpr int Dh  = 64;
constexpr int ID  = 1024;
constexpr float ATT_SCALE = 0.125f;

constexpr size_t NX  = (size_t)Bz * SQ  * QD;
constexpr size_t NCX = (size_t)Bz * SKV * CD;
constexpr size_t NQe = (size_t)Bz * SQ  * ID;
constexpr size_t NKV = (size_t)Bz * SKV * ID;

// ---------------------------------------------------------------------------
// Scratch (__device__ globals; alloc-free rule)
// ---------------------------------------------------------------------------
__device__ __half g_qh[NQe], g_ql[NQe];
__device__ __half g_kh[NKV];
__device__ __half g_vh[NKV], g_vl[NKV];
__device__ __nv_bfloat16 g_aoh[NQe], g_aol[NQe];

__device__ __nv_bfloat16 g_xh[NX],  g_xl[NX];
__device__ __nv_bfloat16 g_ch[NCX], g_cl[NCX];
// Transposed weights, stored [N,K] K-major
__device__ __nv_bfloat16 g_wqh[(size_t)ID*QD], g_wql[(size_t)ID*QD];
__device__ __nv_bfloat16 g_wkh[(size_t)ID*CD], g_wkl[(size_t)ID*CD];
__device__ __nv_bfloat16 g_wvh[(size_t)ID*CD], g_wvl[(size_t)ID*CD];
__device__ __nv_bfloat16 g_woh[(size_t)QD*ID], g_wol[(size_t)QD*ID];

// ---------------------------------------------------------------------------
// PTX helpers (plain sm_103-safe: sm_80-era mma.sync / ldmatrix / cp.async)
// ---------------------------------------------------------------------------
__device__ __forceinline__ uint32_t smem_u32(const void* p) {
    uint32_t a;
    asm("{ .reg .u64 t; cvta.to.shared.u64 t, %1; cvt.u32.u64 %0, t; }"
        : "=r"(a) : "l"(p));
    return a;
}

#define LDSM4(r, addr)                                                        \
    asm volatile("ldmatrix.sync.aligned.m8n8.x4.shared.b16 {%0,%1,%2,%3}, [%4];" \
        : "=r"((r)[0]), "=r"((r)[1]), "=r"((r)[2]), "=r"((r)[3]) : "r"(addr))

#define LDSM4T(r, addr)                                                       \
    asm volatile("ldmatrix.sync.aligned.m8n8.x4.trans.shared.b16 {%0,%1,%2,%3}, [%4];" \
        : "=r"((r)[0]), "=r"((r)[1]), "=r"((r)[2]), "=r"((r)[3]) : "r"(addr))

#define MMA_BF16(c, a, b0, b1)                                                \
    asm volatile("mma.sync.aligned.m16n8k16.row.col.f32.bf16.bf16.f32 "       \
        "{%0,%1,%2,%3}, {%4,%5,%6,%7}, {%8,%9}, {%0,%1,%2,%3};"               \
        : "+f"((c)[0]), "+f"((c)[1]), "+f"((c)[2]), "+f"((c)[3])              \
        : "r"((a)[0]), "r"((a)[1]), "r"((a)[2]), "r"((a)[3]), "r"(b0), "r"(b1))

#define MMA_F16(c, a, b0, b1)                                                 \
    asm volatile("mma.sync.aligned.m16n8k16.row.col.f32.f16.f16.f32 "         \
        "{%0,%1,%2,%3}, {%4,%5,%6,%7}, {%8,%9}, {%0,%1,%2,%3};"               \
        : "+f"((c)[0]), "+f"((c)[1]), "+f"((c)[2]), "+f"((c)[3])              \
        : "r"((a)[0]), "r"((a)[1]), "r"((a)[2]), "r"((a)[3]), "r"(b0), "r"(b1))

#define CP_ASYNC16(daddr, gptr)                                               \
    asm volatile("cp.async.cg.shared.global [%0], [%1], 16;"                  \
        :: "r"(daddr), "l"(gptr))
#define CP_COMMIT() asm volatile("cp.async.commit_group;" ::: "memory")

__device__ __forceinline__ uint32_t pack2h(float a, float b) {
    __half2 h = __floats2half2_rn(a, b);
    return *reinterpret_cast<uint32_t*>(&h);
}

// ---------------------------------------------------------------------------
// fp32 -> (hi, lo) bf16 split, elementwise
// ---------------------------------------------------------------------------
__global__ void splitk(const float* __restrict__ s, __nv_bfloat16* __restrict__ hi,
                       __nv_bfloat16* __restrict__ lo, int n4) {
    int i = blockIdx.x * blockDim.x + threadIdx.x;
    if (i >= n4) return;
    float4 v = ((const float4*)s)[i];
    float a[4] = {v.x, v.y, v.z, v.w};
    __nv_bfloat16 h[4], l[4];
#pragma unroll
    for (int j = 0; j < 4; j++) {
        h[j] = __float2bfloat16(a[j]);
        l[j] = __float2bfloat16(a[j] - __bfloat162float(h[j]));
    }
    ((float2*)hi)[i] = *(float2*)h;
    ((float2*)lo)[i] = *(float2*)l;
}

// ---------------------------------------------------------------------------
// W[K,N] fp32 -> WT[N,K] bf16 hi/lo (tiled transpose + split)
// ---------------------------------------------------------------------------
__global__ void tsplit(const float* __restrict__ W, __nv_bfloat16* __restrict__ hiT,
                       __nv_bfloat16* __restrict__ loT, int K, int N) {
    __shared__ float t[32][33];
    int nb = blockIdx.x * 32, kb = blockIdx.y * 32;
    int tx = threadIdx.x, ty = threadIdx.y;
    for (int r = ty; r < 32; r += 8)
        t[r][tx] = W[(size_t)(kb + r) * N + nb + tx];
    __syncthreads();
    for (int r = ty; r < 32; r += 8) {
        float a = t[tx][r];
        __nv_bfloat16 h = __float2bfloat16(a);
        __nv_bfloat16 l = __float2bfloat16(a - __bfloat162float(h));
        hiT[(size_t)(nb + r) * K + kb + tx] = h;
        loT[(size_t)(nb + r) * K + kb + tx] = l;
    }
}

// ---------------------------------------------------------------------------
// Fused split-bf16 GEMM v2 (cp.async double-buffered, 3 MMA passes per chunk):
//   C = Ahi@Bhi + Alo@Bhi + Ahi@Blo, done per 32-wide k-chunk with tiles
//   resident once in smem. CTA 128x128, 8 warps (2x4), warp 64x32.
//   OM=0: fp32 out + bias; OM=1: fp16 hi/lo; OM=2: fp16 single.
// ---------------------------------------------------------------------------
constexpr int STR = 40;                       // smem pitch in bf16 (80 B rows)
constexpr int TILE_B  = 128 * STR * 2;        // 10240 B per 128x32 tile
constexpr int STAGE_B = 4 * TILE_B;           // Ah | Al | Bh | Bl
constexpr int MMSMEM  = 2 * STAGE_B;          // 81920 B

template <int OM>
__global__ __launch_bounds__(256) void mm_s(
    const __nv_bfloat16* __restrict__ Ahi, const __nv_bfloat16* __restrict__ Alo,
    const __nv_bfloat16* __restrict__ BThi, const __nv_bfloat16* __restrict__ BTlo,
    const float* __restrict__ bias, void* __restrict__ O1, void* __restrict__ O2,
    int M, int N, int K)
{
    extern __shared__ char dsm[];
    const uint32_t sbase = smem_u32(dsm);

    const int tid  = threadIdx.x;
    const int lane = tid & 31;
    const int wid  = tid >> 5;
    const int wm   = wid & 1;
    const int wn   = wid >> 1;
    const int bm = blockIdx.y, bn = blockIdx.x;

    const int g  = lane >> 3, lr = lane & 7;
    const int aRow  = (g & 1) * 8 + lr;
    const int aKoff = (g >> 1) * 16;
    const int bRow  = (g >> 1) * 8 + lr;
    const int bKoff = (g & 1) * 16;

    const uint32_t aOffW = (uint32_t)(wm * 64 + aRow) * (STR * 2) + aKoff;
    const uint32_t bOffW = (uint32_t)(wn * 32 + bRow) * (STR * 2) + bKoff;

    float acc[4][4][4];
#pragma unroll
    for (int i = 0; i < 4; i++)
#pragma unroll
        for (int j = 0; j < 4; j++)
#pragma unroll
            for (int q = 0; q < 4; q++) acc[i][j][q] = 0.f;

    const int kc = K / 32;
    const int r0 = tid >> 2, c4 = (tid & 3) * 8;   // 512 uint4 per tile / 256 thr = 2
    const int r1 = (tid + 256) >> 2, c41 = ((tid + 256) & 3) * 8;
    const uint32_t so0 = (uint32_t)(r0 * STR + c4) * 2;
    const uint32_t so1 = (uint32_t)(r1 * STR + c41) * 2;

    const __nv_bfloat16* Agh = Ahi  + (size_t)(bm * 128) * K;
    const __nv_bfloat16* Agl = Alo  + (size_t)(bm * 128) * K;
    const __nv_bfloat16* Bgh = BThi + (size_t)(bn * 128) * K;
    const __nv_bfloat16* Bgl = BTlo + (size_t)(bn * 128) * K;

    auto issue = [&](int ch, int bi) {
        const int k0 = ch * 32;
        const uint32_t base = sbase + bi * STAGE_B;
        CP_ASYNC16(base + 0 * TILE_B + so0, Agh + (size_t)r0 * K + k0 + c4);
        CP_ASYNC16(base + 0 * TILE_B + so1, Agh + (size_t)r1 * K + k0 + c41);
        CP_ASYNC16(base + 1 * TILE_B + so0, Agl + (size_t)r0 * K + k0 + c4);
        CP_ASYNC16(base + 1 * TILE_B + so1, Agl + (size_t)r1 * K + k0 + c41);
        CP_ASYNC16(base + 2 * TILE_B + so0, Bgh + (size_t)r0 * K + k0 + c4);
        CP_ASYNC16(base + 2 * TILE_B + so1, Bgh + (size_t)r1 * K + k0 + c41);
        CP_ASYNC16(base + 3 * TILE_B + so0, Bgl + (size_t)r0 * K + k0 + c4);
        CP_ASYNC16(base + 3 * TILE_B + so1, Bgl + (size_t)r1 * K + k0 + c41);
        CP_COMMIT();
    };

    issue(0, 0);
    issue(1, 1);

    for (int c = 0; c < kc; ++c) {
        if (c + 1 < kc) asm volatile("cp.async.wait_group 1;" ::: "memory");
        else            asm volatile("cp.async.wait_group 0;" ::: "memory");
        __syncthreads();

        const uint32_t st = sbase + (c & 1) * STAGE_B;
        const uint32_t aHiB = st + 0 * TILE_B + aOffW;
        const uint32_t aLoB = st + 1 * TILE_B + aOffW;
        const uint32_t bHiB = st + 2 * TILE_B + bOffW;
        const uint32_t bLoB = st + 3 * TILE_B + bOffW;

#pragma unroll
        for (int k16 = 0; k16 < 2; k16++) {
            uint32_t ah[4][4], al[4][4];
#pragma unroll
            for (int mi = 0; mi < 4; mi++) {
                LDSM4(ah[mi], aHiB + (uint32_t)(mi * 16) * (STR * 2) + k16 * 32);
                LDSM4(al[mi], aLoB + (uint32_t)(mi * 16) * (STR * 2) + k16 * 32);
            }
#pragma unroll
            for (int j4 = 0; j4 < 2; j4++) {
                uint32_t bh[4], bl[4];
                LDSM4(bh, bHiB + (uint32_t)(j4 * 16) * (STR * 2) + k16 * 32);
                LDSM4(bl, bLoB + (uint32_t)(j4 * 16) * (STR * 2) + k16 * 32);
#pragma unroll
                for (int mi = 0; mi < 4; mi++) {
                    MMA_BF16(acc[mi][2 * j4 + 0], ah[mi], bh[0], bh[1]);
                    MMA_BF16(acc[mi][2 * j4 + 1], ah[mi], bh[2], bh[3]);
                    MMA_BF16(acc[mi][2 * j4 + 0], al[mi], bh[0], bh[1]);
                    MMA_BF16(acc[mi][2 * j4 + 1], al[mi], bh[2], bh[3]);
                    MMA_BF16(acc[mi][2 * j4 + 0], ah[mi], bl[0], bl[1]);
                    MMA_BF16(acc[mi][2 * j4 + 1], ah[mi], bl[2], bl[3]);
                }
            }
        }
        __syncthreads();
        if (c + 2 < kc) issue(c + 2, c & 1);
    }

    const int tr = lane >> 2, tc = (lane & 3) * 2;
#pragma unroll
    for (int mi = 0; mi < 4; mi++) {
#pragma unroll
        for (int nj = 0; nj < 4; nj++) {
            const int row = bm * 128 + wm * 64 + mi * 16 + tr;
            const int col = bn * 128 + wn * 32 + nj * 8 + tc;
#pragma unroll
            for (int half_ = 0; half_ < 2; half_++) {
                const int rr = row + half_ * 8;
                float x0 = acc[mi][nj][half_ * 2 + 0];
                float x1 = acc[mi][nj][half_ * 2 + 1];
                if (OM == 0) {
                    float* C = (float*)O1;
                    float2 v = {x0 + bias[col], x1 + bias[col + 1]};
                    *(float2*)(C + (size_t)rr * N + col) = v;
                } else if (OM == 1) {
                    __half* Ph = (__half*)O1; __half* Pl = (__half*)O2;
                    __half h0 = __float2half_rn(x0);
                    __half h1 = __float2half_rn(x1);
                    __half l0 = __float2half_rn(x0 - __half2float(h0));
                    __half l1 = __float2half_rn(x1 - __half2float(h1));
                    __half2 vh; vh.x = h0; vh.y = h1;
                    __half2 vl; vl.x = l0; vl.y = l1;
                    *(__half2*)(Ph + (size_t)rr * N + col) = vh;
                    *(__half2*)(Pl + (size_t)rr * N + col) = vl;
                } else {
                    __half* Ph = (__half*)O1;
                    __half2 vh; vh.x = __float2half_rn(x0); vh.y = __float2half_rn(x1);
                    *(__half2*)(Ph + (size_t)rr * N + col) = vh;
                }
            }
        }
    }
}

// ---------------------------------------------------------------------------
// Tensor-core flash attention (fp16 mma, fp32 softmax/accum) — unchanged R4
// ---------------------------------------------------------------------------
constexpr int FP = 72;
constexpr int FQ_ELE = 128 * FP;
constexpr int FT_ELE = 64 * FP;
constexpr int FBUF_ELE = 3 * FT_ELE;
constexpr int FSMEM = (2 * FQ_ELE + 2 * FBUF_ELE) * 2;

__global__ __launch_bounds__(256) void flash_mma(
    const __half* __restrict__ Qh, const __half* __restrict__ Ql,
    const __half* __restrict__ Kh,
    const __half* __restrict__ Vh, const __half* __restrict__ Vl,
    __nv_bfloat16* __restrict__ AOh, __nv_bfloat16* __restrict__ AOl)
{
    extern __shared__ __half fsm[];
    __half* sQh = fsm;
    __half* sQl = sQh + FQ_ELE;
    __half* sBuf = sQl + FQ_ELE;

    const int tid  = threadIdx.x;
    const int lane = tid & 31;
    const int w    = tid >> 5;
    const int b  = blockIdx.y >> 4, h = blockIdx.y & 15;
    const size_t bq  = (size_t)b * SQ + blockIdx.x * 128;
    const size_t bkv = (size_t)b * SKV;
    const int hc = h * Dh;

    {
        const int r = tid >> 1, c8 = (tid & 1) * 4;
#pragma unroll
        for (int i = 0; i < 4; i++) {
            int cc = c8 + (i & 3);
            *(uint4*)(sQh + r * FP + cc * 8) =
                *(const uint4*)(Qh + (bq + r) * ID + hc + cc * 8);
            *(uint4*)(sQl + r * FP + cc * 8) =
                *(const uint4*)(Ql + (bq + r) * ID + hc + cc * 8);
        }
    }

    auto issue_tile = [&](int jt, int bi) {
        uint32_t kb  = smem_u32(sBuf + bi * FBUF_ELE);
        uint32_t vhb = kb + FT_ELE * 2;
        uint32_t vlb = vhb + FT_ELE * 2;
        const size_t grow = (bkv + jt * 64) * ID + hc;
#pragma unroll
        for (int i = 0; i < 2; i++) {
            int idx = tid + i * 256;
            int r = idx >> 3, c8 = idx & 7;
            uint32_t so = (uint32_t)(r * FP + c8 * 8) * 2;
            CP_ASYNC16(kb + so, Kh + grow + (size_t)r * ID + c8 * 8);
        }
#pragma unroll
        for (int i = 0; i < 2; i++) {
            int idx = tid + i * 256;
            int r = idx >> 3, c8 = idx & 7;
            uint32_t so = (uint32_t)(r * FP + c8 * 8) * 2;
            CP_ASYNC16(vhb + so, Vh + grow + (size_t)r * ID + c8 * 8);
            CP_ASYNC16(vlb + so, Vl + grow + (size_t)r * ID + c8 * 8);
        }
        CP_COMMIT();
    };

    issue_tile(0, 0);
    __syncthreads();

    const int g2 = lane >> 3, lr = lane & 7;
    const int aRow = (g2 & 1) * 8 + lr, aK = (g2 >> 1) * 16;
    uint32_t qhf[4][4], qlf[4][4];
    {
        uint32_t qhB = smem_u32(sQh) + (uint32_t)(w * 16 + aRow) * (FP * 2) + aK;
        uint32_t qlB = smem_u32(sQl) + (uint32_t)(w * 16 + aRow) * (FP * 2) + aK;
#pragma unroll
        for (int kd = 0; kd < 4; kd++) {
            LDSM4(qhf[kd], qhB + kd * 32);
            LDSM4(qlf[kd], qlB + kd * 32);
        }
    }

    const int bRow = (g2 >> 1) * 8 + lr, bK = (g2 & 1) * 16;
    const int vRow = (g2 & 1) * 8 + lr, vCol = (g2 >> 1) * 8;

    float o[8][4];
#pragma unroll
    for (int j = 0; j < 8; j++)
#pragma unroll
        for (int q = 0; q < 4; q++) o[j][q] = 0.f;
    float m0 = -1e30f, m1 = -1e30f, l0 = 0.f, l1 = 0.f;

    constexpr int NT = SKV / 64;
    for (int jt = 0; jt < NT; jt++) {
        if (jt + 1 < NT) issue_tile(jt + 1, (jt + 1) & 1);
        if (jt == NT - 1) asm volatile("cp.async.wait_group 0;" ::: "memory");
        else              asm volatile("cp.async.wait_group 1;" ::: "memory");
        __syncthreads();

        const int bi = jt & 1;
        const uint32_t kBase  = smem_u32(sBuf + bi * FBUF_ELE) + (uint32_t)bRow * (FP * 2) + bK;
        const uint32_t vhBase = smem_u32(sBuf + bi * FBUF_ELE + FT_ELE) + (uint32_t)vRow * (FP * 2) + vCol * 2;
        const uint32_t vlBase = vhBase + FT_ELE * 2;

        float s[8][4];
#pragma unroll
        for (int j = 0; j < 8; j++)
#pragma unroll
            for (int q = 0; q < 4; q++) s[j][q] = 0.f;

#pragma unroll
        for (int kd = 0; kd < 4; kd++) {
#pragma unroll
            for (int jn = 0; jn < 4; jn++) {
                uint32_t kf[4];
                LDSM4(kf, kBase + (uint32_t)(jn * 16) * (FP * 2) + kd * 32);
                MMA_F16(s[2 * jn + 0], qhf[kd], kf[0], kf[1]);
                MMA_F16(s[2 * jn + 1], qhf[kd], kf[2], kf[3]);
                MMA_F16(s[2 * jn + 0], qlf[kd], kf[0], kf[1]);
                MMA_F16(s[2 * jn + 1], qlf[kd], kf[2], kf[3]);
            }
        }

        float mx0 = -1e30f, mx1 = -1e30f;
#pragma unroll
        for (int j = 0; j < 8; j++) {
            s[j][0] *= ATT_SCALE; s[j][1] *= ATT_SCALE;
            s[j][2] *= ATT_SCALE; s[j][3] *= ATT_SCALE;
            mx0 = fmaxf(mx0, fmaxf(s[j][0], s[j][1]));
            mx1 = fmaxf(mx1, fmaxf(s[j][2], s[j][3]));
        }
        mx0 = fmaxf(mx0, __shfl_xor_sync(0xffffffffu, mx0, 1));
        mx0 = fmaxf(mx0, __shfl_xor_sync(0xffffffffu, mx0, 2));
        mx1 = fmaxf(mx1, __shfl_xor_sync(0xffffffffu, mx1, 1));
        mx1 = fmaxf(mx1, __shfl_xor_sync(0xffffffffu, mx1, 2));

        const float m0n = fmaxf(m0, mx0), m1n = fmaxf(m1, mx1);
        const float f0 = __expf(m0 - m0n), f1 = __expf(m1 - m1n);
        float sum0 = 0.f, sum1 = 0.f;
#pragma unroll
        for (int j = 0; j < 8; j++) {
            s[j][0] = __expf(s[j][0] - m0n); s[j][1] = __expf(s[j][1] - m0n);
            s[j][2] = __expf(s[j][2] - m1n); s[j][3] = __expf(s[j][3] - m1n);
            sum0 += s[j][0] + s[j][1];
            sum1 += s[j][2] + s[j][3];
        }
        sum0 += __shfl_xor_sync(0xffffffffu, sum0, 1);
        sum0 += __shfl_xor_sync(0xffffffffu, sum0, 2);
        sum1 += __shfl_xor_sync(0xffffffffu, sum1, 1);
        sum1 += __shfl_xor_sync(0xffffffffu, sum1, 2);
        l0 = l0 * f0 + sum0;
        l1 = l1 * f1 + sum1;
        m0 = m0n; m1 = m1n;

#pragma unroll
        for (int j = 0; j < 8; j++) {
            o[j][0] *= f0; o[j][1] *= f0;
            o[j][2] *= f1; o[j][3] *= f1;
        }

        uint32_t pf[4][4];
#pragma unroll
        for (int kd = 0; kd < 4; kd++) {
            pf[kd][0] = pack2h(s[2 * kd + 0][0], s[2 * kd + 0][1]);
            pf[kd][1] = pack2h(s[2 * kd + 0][2], s[2 * kd + 0][3]);
            pf[kd][2] = pack2h(s[2 * kd + 1][0], s[2 * kd + 1][1]);
            pf[kd][3] = pack2h(s[2 * kd + 1][2], s[2 * kd + 1][3]);
        }

#pragma unroll
        for (int kd = 0; kd < 4; kd++) {
#pragma unroll
            for (int jn = 0; jn < 4; jn++) {
                uint32_t vf[4];
                LDSM4T(vf, vhBase + (uint32_t)(kd * 16) * (FP * 2) + jn * 32);
                MMA_F16(o[2 * jn + 0], pf[kd], vf[0], vf[1]);
                MMA_F16(o[2 * jn + 1], pf[kd], vf[2], vf[3]);
                LDSM4T(vf, vlBase + (uint32_t)(kd * 16) * (FP * 2) + jn * 32);
                MMA_F16(o[2 * jn + 0], pf[kd], vf[0], vf[1]);
                MMA_F16(o[2 * jn + 1], pf[kd], vf[2], vf[3]);
            }
        }
        __syncthreads();
    }

    const float inv0 = 1.f / l0, inv1 = 1.f / l1;
    const int rg = lane >> 2, tc = (lane & 3) * 2;
#pragma unroll
    for (int j = 0; j < 8; j++) {
        const int col = hc + j * 8 + tc;
#pragma unroll
        for (int half_ = 0; half_ < 2; half_++) {
            const size_t row = bq + w * 16 + rg + half_ * 8;
            float x0 = o[j][half_ * 2 + 0] * (half_ ? inv1 : inv0);
            float x1 = o[j][half_ * 2 + 1] * (half_ ? inv1 : inv0);
            __nv_bfloat16 h0 = __float2bfloat16(x0);
            __nv_bfloat16 h1 = __float2bfloat16(x1);
            __nv_bfloat16 e0 = __float2bfloat16(x0 - __bfloat162float(h0));
            __nv_bfloat16 e1 = __float2bfloat16(x1 - __bfloat162float(h1));
            __nv_bfloat162 vh; vh.x = h0; vh.y = h1;
            __nv_bfloat162 vl; vl.x = e0; vl.y = e1;
            *(__nv_bfloat162*)(AOh + row * ID + col) = vh;
            *(__nv_bfloat162*)(AOl + row * ID + col) = vl;
        }
    }
}

// ---------------------------------------------------------------------------
// Launch
// ---------------------------------------------------------------------------
extern "C" void kernel_launch(void* const* d_in, const int* in_sizes, int n_in,
                              void* d_out, int out_size)
{
    const float* x   = (const float*)d_in[0];
    const float* ctx = (const float*)d_in[1];
    const float* Wq  = (const float*)d_in[2];
    const float* Wk  = (const float*)d_in[3];
    const float* Wv  = (const float*)d_in[4];
    const float* Wo  = (const float*)d_in[5];
    const float* bo  = (const float*)d_in[6];
    float* out = (float*)d_out;

    __half *qh, *ql, *kh, *vh, *vl;
    __nv_bfloat16 *aoh, *aol, *xh, *xl, *ch, *cl;
    __nv_bfloat16 *wqh, *wql, *wkh, *wkl, *wvh, *wvl, *woh, *wol;
    cudaGetSymbolAddress((void**)&qh,  g_qh);  cudaGetSymbolAddress((void**)&ql,  g_ql);
    cudaGetSymbolAddress((void**)&kh,  g_kh);
    cudaGetSymbolAddress((void**)&vh,  g_vh);  cudaGetSymbolAddress((void**)&vl,  g_vl);
    cudaGetSymbolAddress((void**)&aoh, g_aoh); cudaGetSymbolAddress((void**)&aol, g_aol);
    cudaGetSymbolAddress((void**)&xh,  g_xh);  cudaGetSymbolAddress((void**)&xl,  g_xl);
    cudaGetSymbolAddress((void**)&ch,  g_ch);  cudaGetSymbolAddress((void**)&cl,  g_cl);
    cudaGetSymbolAddress((void**)&wqh, g_wqh); cudaGetSymbolAddress((void**)&wql, g_wql);
    cudaGetSymbolAddress((void**)&wkh, g_wkh); cudaGetSymbolAddress((void**)&wkl, g_wkl);
    cudaGetSymbolAddress((void**)&wvh, g_wvh); cudaGetSymbolAddress((void**)&wvl, g_wvl);
    cudaGetSymbolAddress((void**)&woh, g_woh); cudaGetSymbolAddress((void**)&wol, g_wol);

    cudaFuncSetAttribute(flash_mma, cudaFuncAttributeMaxDynamicSharedMemorySize, FSMEM);
    cudaFuncSetAttribute(mm_s<0>, cudaFuncAttributeMaxDynamicSharedMemorySize, MMSMEM);
    cudaFuncSetAttribute(mm_s<1>, cudaFuncAttributeMaxDynamicSharedMemorySize, MMSMEM);
    cudaFuncSetAttribute(mm_s<2>, cudaFuncAttributeMaxDynamicSharedMemorySize, MMSMEM);

    // Input conversions
    splitk<<<(int)(NX  / 4 / 256), 256>>>(x,   xh, xl, (int)(NX  / 4));
    splitk<<<(int)(NCX / 4 / 256), 256>>>(ctx, ch, cl, (int)(NCX / 4));
    tsplit<<<dim3(ID / 32, QD / 32), dim3(32, 8)>>>(Wq, wqh, wql, QD, ID);
    tsplit<<<dim3(ID / 32, CD / 32), dim3(32, 8)>>>(Wk, wkh, wkl, CD, ID);
    tsplit<<<dim3(ID / 32, CD / 32), dim3(32, 8)>>>(Wv, wvh, wvl, CD, ID);
    tsplit<<<dim3(QD / 32, ID / 32), dim3(32, 8)>>>(Wo, woh, wol, ID, QD);

    // Projections: Q -> fp16 hi/lo, K -> fp16, V -> fp16 hi/lo
    mm_s<1><<<dim3(ID / 128, (Bz * SQ)  / 128), 256, MMSMEM>>>(xh, xl, wqh, wql, nullptr, qh, ql, Bz * SQ,  ID, QD);
    mm_s<2><<<dim3(ID / 128, (Bz * SKV) / 128), 256, MMSMEM>>>(ch, cl, wkh, wkl, nullptr, kh, nullptr, Bz * SKV, ID, CD);
    mm_s<1><<<dim3(ID / 128, (Bz * SKV) / 128), 256, MMSMEM>>>(ch, cl, wvh, wvl, nullptr, vh, vl, Bz * SKV, ID, CD);

    // Attention (tensor-core flash) -> bf16 hi/lo
    flash_mma<<<dim3(SQ / 128, Bz * H), 256, FSMEM>>>(qh, ql, kh, vh, vl, aoh, aol);

    // Output projection (+bias) -> fp32
    mm_s<0><<<dim3(QD / 128, (Bz * SQ) / 128), 256, MMSMEM>>>(aoh, aol, woh, wol, bo, out, nullptr, Bz * SQ, QD, ID);
}

// round 6
// speedup vs baseline: 4.1155x; 1.2929x over previous
#include <cuda_runtime.h>
#include <cuda_bf16.h>
#include <cuda_fp16.h>
#include <math.h>
#include <stdint.h>

// ---------------------------------------------------------------------------
// Problem constants
// ---------------------------------------------------------------------------
constexpr int Bz  = 4;
constexpr int SQ  = 4096;
constexpr int SKV = 1024;
constexpr int QD  = 1024;
constexpr int CD  = 768;
constexpr int H   = 16;
constexpr int Dh  = 64;
constexpr int ID  = 1024;
constexpr float ATT_SCALE = 0.125f;

constexpr size_t NX  = (size_t)Bz * SQ  * QD;
constexpr size_t NCX = (size_t)Bz * SKV * CD;
constexpr size_t NQe = (size_t)Bz * SQ  * ID;
constexpr size_t NKV = (size_t)Bz * SKV * ID;

// ---------------------------------------------------------------------------
// Scratch (__device__ globals; alloc-free rule)  — all fp16 now
// ---------------------------------------------------------------------------
__device__ __half g_qh[NQe], g_ql[NQe];
__device__ __half g_kh[NKV];
__device__ __half g_vh[NKV], g_vl[NKV];
__device__ __half g_aoh[NQe], g_aol[NQe];

__device__ __half g_xh[NX],  g_xl[NX];
__device__ __half g_ch[NCX], g_cl[NCX];
// Transposed weights, stored [N,K] K-major, single fp16
__device__ __half g_wq[(size_t)ID*QD];
__device__ __half g_wk[(size_t)ID*CD];
__device__ __half g_wv[(size_t)ID*CD];
__device__ __half g_wo[(size_t)QD*ID];

// ---------------------------------------------------------------------------
// PTX helpers (plain sm_103-safe: sm_80-era mma.sync / ldmatrix / cp.async)
// ---------------------------------------------------------------------------
__device__ __forceinline__ uint32_t smem_u32(const void* p) {
    uint32_t a;
    asm("{ .reg .u64 t; cvta.to.shared.u64 t, %1; cvt.u32.u64 %0, t; }"
        : "=r"(a) : "l"(p));
    return a;
}

#define LDSM4(r, addr)                                                        \
    asm volatile("ldmatrix.sync.aligned.m8n8.x4.shared.b16 {%0,%1,%2,%3}, [%4];" \
        : "=r"((r)[0]), "=r"((r)[1]), "=r"((r)[2]), "=r"((r)[3]) : "r"(addr))

#define LDSM4T(r, addr)                                                       \
    asm volatile("ldmatrix.sync.aligned.m8n8.x4.trans.shared.b16 {%0,%1,%2,%3}, [%4];" \
        : "=r"((r)[0]), "=r"((r)[1]), "=r"((r)[2]), "=r"((r)[3]) : "r"(addr))

#define MMA_F16(c, a, b0, b1)                                                 \
    asm volatile("mma.sync.aligned.m16n8k16.row.col.f32.f16.f16.f32 "         \
        "{%0,%1,%2,%3}, {%4,%5,%6,%7}, {%8,%9}, {%0,%1,%2,%3};"               \
        : "+f"((c)[0]), "+f"((c)[1]), "+f"((c)[2]), "+f"((c)[3])              \
        : "r"((a)[0]), "r"((a)[1]), "r"((a)[2]), "r"((a)[3]), "r"(b0), "r"(b1))

#define CP_ASYNC16(daddr, gptr)                                               \
    asm volatile("cp.async.cg.shared.global [%0], [%1], 16;"                  \
        :: "r"(daddr), "l"(gptr))
#define CP_COMMIT() asm volatile("cp.async.commit_group;" ::: "memory")

__device__ __forceinline__ uint32_t pack2h(float a, float b) {
    __half2 h = __floats2half2_rn(a, b);
    return *reinterpret_cast<uint32_t*>(&h);
}

// ---------------------------------------------------------------------------
// fp32 -> (hi, lo) fp16 split, elementwise
// ---------------------------------------------------------------------------
__global__ void splitk(const float* __restrict__ s, __half* __restrict__ hi,
                       __half* __restrict__ lo, int n4) {
    int i = blockIdx.x * blockDim.x + threadIdx.x;
    if (i >= n4) return;
    float4 v = ((const float4*)s)[i];
    float a[4] = {v.x, v.y, v.z, v.w};
    __half h[4], l[4];
#pragma unroll
    for (int j = 0; j < 4; j++) {
        h[j] = __float2half_rn(a[j]);
        l[j] = __float2half_rn(a[j] - __half2float(h[j]));
    }
    ((float2*)hi)[i] = *(float2*)h;
    ((float2*)lo)[i] = *(float2*)l;
}

// ---------------------------------------------------------------------------
// W[K,N] fp32 -> WT[N,K] fp16 (tiled transpose)
// ---------------------------------------------------------------------------
__global__ void tsp_h(const float* __restrict__ W, __half* __restrict__ T,
                      int K, int N) {
    __shared__ float t[32][33];
    int nb = blockIdx.x * 32, kb = blockIdx.y * 32;
    int tx = threadIdx.x, ty = threadIdx.y;
    for (int r = ty; r < 32; r += 8)
        t[r][tx] = W[(size_t)(kb + r) * N + nb + tx];
    __syncthreads();
    for (int r = ty; r < 32; r += 8)
        T[(size_t)(nb + r) * K + kb + tx] = __float2half_rn(t[tx][r]);
}

// ---------------------------------------------------------------------------
// fp16-split GEMM (2 passes fused): C = (Ahi + Alo) @ B
//   A as fp16 hi/lo [M,K]; B transposed fp16 [N,K]. cp.async double-buffered.
//   CTA 128x128, 8 warps (2x4), warp 64x32.
//   OM=0: fp32 out + bias; OM=1: fp16 hi/lo; OM=2: fp16 single.
// ---------------------------------------------------------------------------
constexpr int STR = 40;                       // smem pitch in halves (80 B rows)
constexpr int TILE_B  = 128 * STR * 2;        // 10240 B per 128x32 tile
constexpr int STAGE_B = 3 * TILE_B;           // Ah | Al | B
constexpr int MMSMEM  = 2 * STAGE_B;          // 61440 B

template <int OM>
__global__ __launch_bounds__(256) void mm_s(
    const __half* __restrict__ Ahi, const __half* __restrict__ Alo,
    const __half* __restrict__ BT,
    const float* __restrict__ bias, void* __restrict__ O1, void* __restrict__ O2,
    int M, int N, int K)
{
    extern __shared__ char dsm[];
    const uint32_t sbase = smem_u32(dsm);

    const int tid  = threadIdx.x;
    const int lane = tid & 31;
    const int wid  = tid >> 5;
    const int wm   = wid & 1;
    const int wn   = wid >> 1;
    const int bm = blockIdx.y, bn = blockIdx.x;

    const int g  = lane >> 3, lr = lane & 7;
    const int aRow  = (g & 1) * 8 + lr;
    const int aKoff = (g >> 1) * 16;
    const int bRow  = (g >> 1) * 8 + lr;
    const int bKoff = (g & 1) * 16;

    const uint32_t aOffW = (uint32_t)(wm * 64 + aRow) * (STR * 2) + aKoff;
    const uint32_t bOffW = (uint32_t)(wn * 32 + bRow) * (STR * 2) + bKoff;

    float acc[4][4][4];
#pragma unroll
    for (int i = 0; i < 4; i++)
#pragma unroll
        for (int j = 0; j < 4; j++)
#pragma unroll
            for (int q = 0; q < 4; q++) acc[i][j][q] = 0.f;

    const int kc = K / 32;
    const int r0 = tid >> 2, c4 = (tid & 3) * 8;
    const int r1 = (tid + 256) >> 2, c41 = ((tid + 256) & 3) * 8;
    const uint32_t so0 = (uint32_t)(r0 * STR + c4) * 2;
    const uint32_t so1 = (uint32_t)(r1 * STR + c41) * 2;

    const __half* Agh = Ahi + (size_t)(bm * 128) * K;
    const __half* Agl = Alo + (size_t)(bm * 128) * K;
    const __half* Bg  = BT  + (size_t)(bn * 128) * K;

    auto issue = [&](int ch, int bi) {
        const int k0 = ch * 32;
        const uint32_t base = sbase + bi * STAGE_B;
        CP_ASYNC16(base + 0 * TILE_B + so0, Agh + (size_t)r0 * K + k0 + c4);
        CP_ASYNC16(base + 0 * TILE_B + so1, Agh + (size_t)r1 * K + k0 + c41);
        CP_ASYNC16(base + 1 * TILE_B + so0, Agl + (size_t)r0 * K + k0 + c4);
        CP_ASYNC16(base + 1 * TILE_B + so1, Agl + (size_t)r1 * K + k0 + c41);
        CP_ASYNC16(base + 2 * TILE_B + so0, Bg  + (size_t)r0 * K + k0 + c4);
        CP_ASYNC16(base + 2 * TILE_B + so1, Bg  + (size_t)r1 * K + k0 + c41);
        CP_COMMIT();
    };

    issue(0, 0);
    issue(1, 1);

    for (int c = 0; c < kc; ++c) {
        if (c + 1 < kc) asm volatile("cp.async.wait_group 1;" ::: "memory");
        else            asm volatile("cp.async.wait_group 0;" ::: "memory");
        __syncthreads();

        const uint32_t st = sbase + (c & 1) * STAGE_B;
        const uint32_t aHiB = st + 0 * TILE_B + aOffW;
        const uint32_t aLoB = st + 1 * TILE_B + aOffW;
        const uint32_t bB   = st + 2 * TILE_B + bOffW;

#pragma unroll
        for (int k16 = 0; k16 < 2; k16++) {
            uint32_t ah[4][4], al[4][4];
#pragma unroll
            for (int mi = 0; mi < 4; mi++) {
                LDSM4(ah[mi], aHiB + (uint32_t)(mi * 16) * (STR * 2) + k16 * 32);
                LDSM4(al[mi], aLoB + (uint32_t)(mi * 16) * (STR * 2) + k16 * 32);
            }
#pragma unroll
            for (int j4 = 0; j4 < 2; j4++) {
                uint32_t bh[4];
                LDSM4(bh, bB + (uint32_t)(j4 * 16) * (STR * 2) + k16 * 32);
#pragma unroll
                for (int mi = 0; mi < 4; mi++) {
                    MMA_F16(acc[mi][2 * j4 + 0], ah[mi], bh[0], bh[1]);
                    MMA_F16(acc[mi][2 * j4 + 1], ah[mi], bh[2], bh[3]);
                    MMA_F16(acc[mi][2 * j4 + 0], al[mi], bh[0], bh[1]);
                    MMA_F16(acc[mi][2 * j4 + 1], al[mi], bh[2], bh[3]);
                }
            }
        }
        __syncthreads();
        if (c + 2 < kc) issue(c + 2, c & 1);
    }

    const int tr = lane >> 2, tc = (lane & 3) * 2;
#pragma unroll
    for (int mi = 0; mi < 4; mi++) {
#pragma unroll
        for (int nj = 0; nj < 4; nj++) {
            const int row = bm * 128 + wm * 64 + mi * 16 + tr;
            const int col = bn * 128 + wn * 32 + nj * 8 + tc;
#pragma unroll
            for (int half_ = 0; half_ < 2; half_++) {
                const int rr = row + half_ * 8;
                float x0 = acc[mi][nj][half_ * 2 + 0];
                float x1 = acc[mi][nj][half_ * 2 + 1];
                if (OM == 0) {
                    float* C = (float*)O1;
                    float2 v = {x0 + bias[col], x1 + bias[col + 1]};
                    *(float2*)(C + (size_t)rr * N + col) = v;
                } else if (OM == 1) {
                    __half* Ph = (__half*)O1; __half* Pl = (__half*)O2;
                    __half h0 = __float2half_rn(x0);
                    __half h1 = __float2half_rn(x1);
                    __half l0 = __float2half_rn(x0 - __half2float(h0));
                    __half l1 = __float2half_rn(x1 - __half2float(h1));
                    __half2 vh; vh.x = h0; vh.y = h1;
                    __half2 vl; vl.x = l0; vl.y = l1;
                    *(__half2*)(Ph + (size_t)rr * N + col) = vh;
                    *(__half2*)(Pl + (size_t)rr * N + col) = vl;
                } else {
                    __half* Ph = (__half*)O1;
                    __half2 vh; vh.x = __float2half_rn(x0); vh.y = __float2half_rn(x1);
                    *(__half2*)(Ph + (size_t)rr * N + col) = vh;
                }
            }
        }
    }
}

// ---------------------------------------------------------------------------
// Tensor-core flash attention (fp16 mma, fp32 softmax/accum)
//   AO now emitted as fp16 hi/lo for the fp16-split O-projection.
// ---------------------------------------------------------------------------
constexpr int FP = 72;
constexpr int FQ_ELE = 128 * FP;
constexpr int FT_ELE = 64 * FP;
constexpr int FBUF_ELE = 3 * FT_ELE;
constexpr int FSMEM = (2 * FQ_ELE + 2 * FBUF_ELE) * 2;

__global__ __launch_bounds__(256) void flash_mma(
    const __half* __restrict__ Qh, const __half* __restrict__ Ql,
    const __half* __restrict__ Kh,
    const __half* __restrict__ Vh, const __half* __restrict__ Vl,
    __half* __restrict__ AOh, __half* __restrict__ AOl)
{
    extern __shared__ __half fsm[];
    __half* sQh = fsm;
    __half* sQl = sQh + FQ_ELE;
    __half* sBuf = sQl + FQ_ELE;

    const int tid  = threadIdx.x;
    const int lane = tid & 31;
    const int w    = tid >> 5;
    const int b  = blockIdx.y >> 4, h = blockIdx.y & 15;
    const size_t bq  = (size_t)b * SQ + blockIdx.x * 128;
    const size_t bkv = (size_t)b * SKV;
    const int hc = h * Dh;

    {
        const int r = tid >> 1, c8 = (tid & 1) * 4;
#pragma unroll
        for (int i = 0; i < 4; i++) {
            int cc = c8 + (i & 3);
            *(uint4*)(sQh + r * FP + cc * 8) =
                *(const uint4*)(Qh + (bq + r) * ID + hc + cc * 8);
            *(uint4*)(sQl + r * FP + cc * 8) =
                *(const uint4*)(Ql + (bq + r) * ID + hc + cc * 8);
        }
    }

    auto issue_tile = [&](int jt, int bi) {
        uint32_t kb  = smem_u32(sBuf + bi * FBUF_ELE);
        uint32_t vhb = kb + FT_ELE * 2;
        uint32_t vlb = vhb + FT_ELE * 2;
        const size_t grow = (bkv + jt * 64) * ID + hc;
#pragma unroll
        for (int i = 0; i < 2; i++) {
            int idx = tid + i * 256;
            int r = idx >> 3, c8 = idx & 7;
            uint32_t so = (uint32_t)(r * FP + c8 * 8) * 2;
            CP_ASYNC16(kb + so, Kh + grow + (size_t)r * ID + c8 * 8);
        }
#pragma unroll
        for (int i = 0; i < 2; i++) {
            int idx = tid + i * 256;
            int r = idx >> 3, c8 = idx & 7;
            uint32_t so = (uint32_t)(r * FP + c8 * 8) * 2;
            CP_ASYNC16(vhb + so, Vh + grow + (size_t)r * ID + c8 * 8);
            CP_ASYNC16(vlb + so, Vl + grow + (size_t)r * ID + c8 * 8);
        }
        CP_COMMIT();
    };

    issue_tile(0, 0);
    __syncthreads();

    const int g2 = lane >> 3, lr = lane & 7;
    const int aRow = (g2 & 1) * 8 + lr, aK = (g2 >> 1) * 16;
    uint32_t qhf[4][4], qlf[4][4];
    {
        uint32_t qhB = smem_u32(sQh) + (uint32_t)(w * 16 + aRow) * (FP * 2) + aK;
        uint32_t qlB = smem_u32(sQl) + (uint32_t)(w * 16 + aRow) * (FP * 2) + aK;
#pragma unroll
        for (int kd = 0; kd < 4; kd++) {
            LDSM4(qhf[kd], qhB + kd * 32);
            LDSM4(qlf[kd], qlB + kd * 32);
        }
    }

    const int bRow = (g2 >> 1) * 8 + lr, bK = (g2 & 1) * 16;
    const int vRow = (g2 & 1) * 8 + lr, vCol = (g2 >> 1) * 8;

    float o[8][4];
#pragma unroll
    for (int j = 0; j < 8; j++)
#pragma unroll
        for (int q = 0; q < 4; q++) o[j][q] = 0.f;
    float m0 = -1e30f, m1 = -1e30f, l0 = 0.f, l1 = 0.f;

    constexpr int NT = SKV / 64;
    for (int jt = 0; jt < NT; jt++) {
        if (jt + 1 < NT) issue_tile(jt + 1, (jt + 1) & 1);
        if (jt == NT - 1) asm volatile("cp.async.wait_group 0;" ::: "memory");
        else              asm volatile("cp.async.wait_group 1;" ::: "memory");
        __syncthreads();

        const int bi = jt & 1;
        const uint32_t kBase  = smem_u32(sBuf + bi * FBUF_ELE) + (uint32_t)bRow * (FP * 2) + bK;
        const uint32_t vhBase = smem_u32(sBuf + bi * FBUF_ELE + FT_ELE) + (uint32_t)vRow * (FP * 2) + vCol * 2;
        const uint32_t vlBase = vhBase + FT_ELE * 2;

        float s[8][4];
#pragma unroll
        for (int j = 0; j < 8; j++)
#pragma unroll
            for (int q = 0; q < 4; q++) s[j][q] = 0.f;

#pragma unroll
        for (int kd = 0; kd < 4; kd++) {
#pragma unroll
            for (int jn = 0; jn < 4; jn++) {
                uint32_t kf[4];
                LDSM4(kf, kBase + (uint32_t)(jn * 16) * (FP * 2) + kd * 32);
                MMA_F16(s[2 * jn + 0], qhf[kd], kf[0], kf[1]);
                MMA_F16(s[2 * jn + 1], qhf[kd], kf[2], kf[3]);
                MMA_F16(s[2 * jn + 0], qlf[kd], kf[0], kf[1]);
                MMA_F16(s[2 * jn + 1], qlf[kd], kf[2], kf[3]);
            }
        }

        float mx0 = -1e30f, mx1 = -1e30f;
#pragma unroll
        for (int j = 0; j < 8; j++) {
            s[j][0] *= ATT_SCALE; s[j][1] *= ATT_SCALE;
            s[j][2] *= ATT_SCALE; s[j][3] *= ATT_SCALE;
            mx0 = fmaxf(mx0, fmaxf(s[j][0], s[j][1]));
            mx1 = fmaxf(mx1, fmaxf(s[j][2], s[j][3]));
        }
        mx0 = fmaxf(mx0, __shfl_xor_sync(0xffffffffu, mx0, 1));
        mx0 = fmaxf(mx0, __shfl_xor_sync(0xffffffffu, mx0, 2));
        mx1 = fmaxf(mx1, __shfl_xor_sync(0xffffffffu, mx1, 1));
        mx1 = fmaxf(mx1, __shfl_xor_sync(0xffffffffu, mx1, 2));

        const float m0n = fmaxf(m0, mx0), m1n = fmaxf(m1, mx1);
        const float f0 = __expf(m0 - m0n), f1 = __expf(m1 - m1n);
        float sum0 = 0.f, sum1 = 0.f;
#pragma unroll
        for (int j = 0; j < 8; j++) {
            s[j][0] = __expf(s[j][0] - m0n); s[j][1] = __expf(s[j][1] - m0n);
            s[j][2] = __expf(s[j][2] - m1n); s[j][3] = __expf(s[j][3] - m1n);
            sum0 += s[j][0] + s[j][1];
            sum1 += s[j][2] + s[j][3];
        }
        sum0 += __shfl_xor_sync(0xffffffffu, sum0, 1);
        sum0 += __shfl_xor_sync(0xffffffffu, sum0, 2);
        sum1 += __shfl_xor_sync(0xffffffffu, sum1, 1);
        sum1 += __shfl_xor_sync(0xffffffffu, sum1, 2);
        l0 = l0 * f0 + sum0;
        l1 = l1 * f1 + sum1;
        m0 = m0n; m1 = m1n;

#pragma unroll
        for (int j = 0; j < 8; j++) {
            o[j][0] *= f0; o[j][1] *= f0;
            o[j][2] *= f1; o[j][3] *= f1;
        }

        uint32_t pf[4][4];
#pragma unroll
        for (int kd = 0; kd < 4; kd++) {
            pf[kd][0] = pack2h(s[2 * kd + 0][0], s[2 * kd + 0][1]);
            pf[kd][1] = pack2h(s[2 * kd + 0][2], s[2 * kd + 0][3]);
            pf[kd][2] = pack2h(s[2 * kd + 1][0], s[2 * kd + 1][1]);
            pf[kd][3] = pack2h(s[2 * kd + 1][2], s[2 * kd + 1][3]);
        }

#pragma unroll
        for (int kd = 0; kd < 4; kd++) {
#pragma unroll
            for (int jn = 0; jn < 4; jn++) {
                uint32_t vf[4];
                LDSM4T(vf, vhBase + (uint32_t)(kd * 16) * (FP * 2) + jn * 32);
                MMA_F16(o[2 * jn + 0], pf[kd], vf[0], vf[1]);
                MMA_F16(o[2 * jn + 1], pf[kd], vf[2], vf[3]);
                LDSM4T(vf, vlBase + (uint32_t)(kd * 16) * (FP * 2) + jn * 32);
                MMA_F16(o[2 * jn + 0], pf[kd], vf[0], vf[1]);
                MMA_F16(o[2 * jn + 1], pf[kd], vf[2], vf[3]);
            }
        }
        __syncthreads();
    }

    const float inv0 = 1.f / l0, inv1 = 1.f / l1;
    const int rg = lane >> 2, tc = (lane & 3) * 2;
#pragma unroll
    for (int j = 0; j < 8; j++) {
        const int col = hc + j * 8 + tc;
#pragma unroll
        for (int half_ = 0; half_ < 2; half_++) {
            const size_t row = bq + w * 16 + rg + half_ * 8;
            float x0 = o[j][half_ * 2 + 0] * (half_ ? inv1 : inv0);
            float x1 = o[j][half_ * 2 + 1] * (half_ ? inv1 : inv0);
            __half h0 = __float2half_rn(x0);
            __half h1 = __float2half_rn(x1);
            __half e0 = __float2half_rn(x0 - __half2float(h0));
            __half e1 = __float2half_rn(x1 - __half2float(h1));
            __half2 vh; vh.x = h0; vh.y = h1;
            __half2 vl; vl.x = e0; vl.y = e1;
            *(__half2*)(AOh + row * ID + col) = vh;
            *(__half2*)(AOl + row * ID + col) = vl;
        }
    }
}

// ---------------------------------------------------------------------------
// Launch
// ---------------------------------------------------------------------------
extern "C" void kernel_launch(void* const* d_in, const int* in_sizes, int n_in,
                              void* d_out, int out_size)
{
    const float* x   = (const float*)d_in[0];
    const float* ctx = (const float*)d_in[1];
    const float* Wq  = (const float*)d_in[2];
    const float* Wk  = (const float*)d_in[3];
    const float* Wv  = (const float*)d_in[4];
    const float* Wo  = (const float*)d_in[5];
    const float* bo  = (const float*)d_in[6];
    float* out = (float*)d_out;

    __half *qh, *ql, *kh, *vh, *vl, *aoh, *aol, *xh, *xl, *ch, *cl;
    __half *wq, *wk, *wv, *wo;
    cudaGetSymbolAddress((void**)&qh,  g_qh);  cudaGetSymbolAddress((void**)&ql,  g_ql);
    cudaGetSymbolAddress((void**)&kh,  g_kh);
    cudaGetSymbolAddress((void**)&vh,  g_vh);  cudaGetSymbolAddress((void**)&vl,  g_vl);
    cudaGetSymbolAddress((void**)&aoh, g_aoh); cudaGetSymbolAddress((void**)&aol, g_aol);
    cudaGetSymbolAddress((void**)&xh,  g_xh);  cudaGetSymbolAddress((void**)&xl,  g_xl);
    cudaGetSymbolAddress((void**)&ch,  g_ch);  cudaGetSymbolAddress((void**)&cl,  g_cl);
    cudaGetSymbolAddress((void**)&wq,  g_wq);  cudaGetSymbolAddress((void**)&wk,  g_wk);
    cudaGetSymbolAddress((void**)&wv,  g_wv);  cudaGetSymbolAddress((void**)&wo,  g_wo);

    cudaFuncSetAttribute(flash_mma, cudaFuncAttributeMaxDynamicSharedMemorySize, FSMEM);
    cudaFuncSetAttribute(mm_s<0>, cudaFuncAttributeMaxDynamicSharedMemorySize, MMSMEM);
    cudaFuncSetAttribute(mm_s<1>, cudaFuncAttributeMaxDynamicSharedMemorySize, MMSMEM);
    cudaFuncSetAttribute(mm_s<2>, cudaFuncAttributeMaxDynamicSharedMemorySize, MMSMEM);

    // Input conversions (fp16 split / fp16 transposed weights)
    splitk<<<(int)(NX  / 4 / 256), 256>>>(x,   xh, xl, (int)(NX  / 4));
    splitk<<<(int)(NCX / 4 / 256), 256>>>(ctx, ch, cl, (int)(NCX / 4));
    tsp_h<<<dim3(ID / 32, QD / 32), dim3(32, 8)>>>(Wq, wq, QD, ID);
    tsp_h<<<dim3(ID / 32, CD / 32), dim3(32, 8)>>>(Wk, wk, CD, ID);
    tsp_h<<<dim3(ID / 32, CD / 32), dim3(32, 8)>>>(Wv, wv, CD, ID);
    tsp_h<<<dim3(QD / 32, ID / 32), dim3(32, 8)>>>(Wo, wo, ID, QD);

    // Projections (2-pass fp16 split): Q -> fp16 hi/lo, K -> fp16, V -> fp16 hi/lo
    mm_s<1><<<dim3(ID / 128, (Bz * SQ)  / 128), 256, MMSMEM>>>(xh, xl, wq, nullptr, qh, ql, Bz * SQ,  ID, QD);
    mm_s<2><<<dim3(ID / 128, (Bz * SKV) / 128), 256, MMSMEM>>>(ch, cl, wk, nullptr, kh, nullptr, Bz * SKV, ID, CD);
    mm_s<1><<<dim3(ID / 128, (Bz * SKV) / 128), 256, MMSMEM>>>(ch, cl, wv, nullptr, vh, vl, Bz * SKV, ID, CD);

    // Attention (tensor-core flash) -> fp16 hi/lo
    flash_mma<<<dim3(SQ / 128, Bz * H), 256, FSMEM>>>(qh, ql, kh, vh, vl, aoh, aol);

    // Output projection (+bias) -> fp32
    mm_s<0><<<dim3(QD / 128, (Bz * SQ) / 128), 256, MMSMEM>>>(aoh, aol, wo, bo, out, nullptr, Bz * SQ, QD, ID);
}

// round 7
// speedup vs baseline: 4.3722x; 1.0624x over previous
#include <cuda_runtime.h>
#include <cuda_bf16.h>
#include <cuda_fp16.h>
#include <math.h>
#include <stdint.h>

// ---------------------------------------------------------------------------
// Problem constants
// ---------------------------------------------------------------------------
constexpr int Bz  = 4;
constexpr int SQ  = 4096;
constexpr int SKV = 1024;
constexpr int QD  = 1024;
constexpr int CD  = 768;
constexpr int H   = 16;
constexpr int Dh  = 64;
constexpr int ID  = 1024;
constexpr float ATT_SCALE = 0.125f;

constexpr size_t NX  = (size_t)Bz * SQ  * QD;
constexpr size_t NCX = (size_t)Bz * SKV * CD;
constexpr size_t NQe = (size_t)Bz * SQ  * ID;
constexpr size_t NKV = (size_t)Bz * SKV * ID;

// ---------------------------------------------------------------------------
// Scratch (__device__ globals; alloc-free rule) — fp16
// ---------------------------------------------------------------------------
__device__ __half g_qh[NQe], g_ql[NQe];
__device__ __half g_kh[NKV];
__device__ __half g_vh[NKV], g_vl[NKV];
__device__ __half g_ao[NQe];                  // attention out, single fp16

__device__ __half g_xh[NX],  g_xl[NX];
__device__ __half g_ch[NCX], g_cl[NCX];
__device__ __half g_wq[(size_t)ID*QD];
__device__ __half g_wk[(size_t)ID*CD];
__device__ __half g_wv[(size_t)ID*CD];
__device__ __half g_wo[(size_t)QD*ID];

// ---------------------------------------------------------------------------
// PTX helpers
// ---------------------------------------------------------------------------
__device__ __forceinline__ uint32_t smem_u32(const void* p) {
    uint32_t a;
    asm("{ .reg .u64 t; cvta.to.shared.u64 t, %1; cvt.u32.u64 %0, t; }"
        : "=r"(a) : "l"(p));
    return a;
}

#define LDSM4(r, addr)                                                        \
    asm volatile("ldmatrix.sync.aligned.m8n8.x4.shared.b16 {%0,%1,%2,%3}, [%4];" \
        : "=r"((r)[0]), "=r"((r)[1]), "=r"((r)[2]), "=r"((r)[3]) : "r"(addr))

#define LDSM4T(r, addr)                                                       \
    asm volatile("ldmatrix.sync.aligned.m8n8.x4.trans.shared.b16 {%0,%1,%2,%3}, [%4];" \
        : "=r"((r)[0]), "=r"((r)[1]), "=r"((r)[2]), "=r"((r)[3]) : "r"(addr))

#define MMA_F16(c, a, b0, b1)                                                 \
    asm volatile("mma.sync.aligned.m16n8k16.row.col.f32.f16.f16.f32 "         \
        "{%0,%1,%2,%3}, {%4,%5,%6,%7}, {%8,%9}, {%0,%1,%2,%3};"               \
        : "+f"((c)[0]), "+f"((c)[1]), "+f"((c)[2]), "+f"((c)[3])              \
        : "r"((a)[0]), "r"((a)[1]), "r"((a)[2]), "r"((a)[3]), "r"(b0), "r"(b1))

#define CP_ASYNC16(daddr, gptr)                                               \
    asm volatile("cp.async.cg.shared.global [%0], [%1], 16;"                  \
        :: "r"(daddr), "l"(gptr))
#define CP_COMMIT() asm volatile("cp.async.commit_group;" ::: "memory")

__device__ __forceinline__ uint32_t pack2h(float a, float b) {
    __half2 h = __floats2half2_rn(a, b);
    return *reinterpret_cast<uint32_t*>(&h);
}

// ---------------------------------------------------------------------------
// fp32 -> (hi, lo) fp16 split
// ---------------------------------------------------------------------------
__global__ void splitk(const float* __restrict__ s, __half* __restrict__ hi,
                       __half* __restrict__ lo, int n4) {
    int i = blockIdx.x * blockDim.x + threadIdx.x;
    if (i >= n4) return;
    float4 v = ((const float4*)s)[i];
    float a[4] = {v.x, v.y, v.z, v.w};
    __half h[4], l[4];
#pragma unroll
    for (int j = 0; j < 4; j++) {
        h[j] = __float2half_rn(a[j]);
        l[j] = __float2half_rn(a[j] - __half2float(h[j]));
    }
    ((float2*)hi)[i] = *(float2*)h;
    ((float2*)lo)[i] = *(float2*)l;
}

// W[K,N] fp32 -> WT[N,K] fp16
__global__ void tsp_h(const float* __restrict__ W, __half* __restrict__ T,
                      int K, int N) {
    __shared__ float t[32][33];
    int nb = blockIdx.x * 32, kb = blockIdx.y * 32;
    int tx = threadIdx.x, ty = threadIdx.y;
    for (int r = ty; r < 32; r += 8)
        t[r][tx] = W[(size_t)(kb + r) * N + nb + tx];
    __syncthreads();
    for (int r = ty; r < 32; r += 8)
        T[(size_t)(nb + r) * K + kb + tx] = __float2half_rn(t[tx][r]);
}

// ---------------------------------------------------------------------------
// GEMM core: acc += (Ahi [+ Alo]) @ B over K. 3-stage cp.async ring,
// one __syncthreads per chunk. CTA 128x128, 8 warps (2x4), warp 64x32.
// smem slots per stage: 0=Ah, 1=Al, 2=B (slot 1 unused when NPASS==1).
// ---------------------------------------------------------------------------
constexpr int STR     = 40;                  // smem pitch (halves)
constexpr int TILE_B  = 128 * STR * 2;       // 10240 B
constexpr int STAGE_B = 3 * TILE_B;          // 30720 B
constexpr int MMSMEM  = 3 * STAGE_B;         // 92160 B

template <int NPASS>
__device__ __forceinline__ void mm_core(
    const __half* __restrict__ Agh, const __half* __restrict__ Agl,
    const __half* __restrict__ Bg, int K,
    uint32_t sbase, int tid, uint32_t aOffW, uint32_t bOffW,
    float acc[4][4][4])
{
    const int kc = K / 32;
    const int r0 = tid >> 2, c4 = (tid & 3) * 8;
    const int r1 = (tid + 256) >> 2, c41 = ((tid + 256) & 3) * 8;
    const uint32_t so0 = (uint32_t)(r0 * STR + c4) * 2;
    const uint32_t so1 = (uint32_t)(r1 * STR + c41) * 2;

    auto issue = [&](int ch, int st3) {
        const int k0 = ch * 32;
        const uint32_t base = sbase + st3 * STAGE_B;
        CP_ASYNC16(base + 0 * TILE_B + so0, Agh + (size_t)r0 * K + k0 + c4);
        CP_ASYNC16(base + 0 * TILE_B + so1, Agh + (size_t)r1 * K + k0 + c41);
        if (NPASS == 2) {
            CP_ASYNC16(base + 1 * TILE_B + so0, Agl + (size_t)r0 * K + k0 + c4);
            CP_ASYNC16(base + 1 * TILE_B + so1, Agl + (size_t)r1 * K + k0 + c41);
        }
        CP_ASYNC16(base + 2 * TILE_B + so0, Bg + (size_t)r0 * K + k0 + c4);
        CP_ASYNC16(base + 2 * TILE_B + so1, Bg + (size_t)r1 * K + k0 + c41);
        CP_COMMIT();
    };

    issue(0, 0);
    issue(1, 1);

    for (int c = 0; c < kc; ++c) {
        if (c + 1 < kc) asm volatile("cp.async.wait_group 1;" ::: "memory");
        else            asm volatile("cp.async.wait_group 0;" ::: "memory");
        __syncthreads();
        if (c + 2 < kc) issue(c + 2, (c + 2) % 3);

        const uint32_t st = sbase + (c % 3) * STAGE_B;
        const uint32_t aHiB = st + 0 * TILE_B + aOffW;
        const uint32_t aLoB = st + 1 * TILE_B + aOffW;
        const uint32_t bB   = st + 2 * TILE_B + bOffW;

#pragma unroll
        for (int k16 = 0; k16 < 2; k16++) {
            uint32_t ah[4][4], al[4][4];
#pragma unroll
            for (int mi = 0; mi < 4; mi++) {
                LDSM4(ah[mi], aHiB + (uint32_t)(mi * 16) * (STR * 2) + k16 * 32);
                if (NPASS == 2)
                    LDSM4(al[mi], aLoB + (uint32_t)(mi * 16) * (STR * 2) + k16 * 32);
            }
#pragma unroll
            for (int j4 = 0; j4 < 2; j4++) {
                uint32_t bh[4];
                LDSM4(bh, bB + (uint32_t)(j4 * 16) * (STR * 2) + k16 * 32);
#pragma unroll
                for (int mi = 0; mi < 4; mi++) {
                    MMA_F16(acc[mi][2 * j4 + 0], ah[mi], bh[0], bh[1]);
                    MMA_F16(acc[mi][2 * j4 + 1], ah[mi], bh[2], bh[3]);
                    if (NPASS == 2) {
                        MMA_F16(acc[mi][2 * j4 + 0], al[mi], bh[0], bh[1]);
                        MMA_F16(acc[mi][2 * j4 + 1], al[mi], bh[2], bh[3]);
                    }
                }
            }
        }
    }
}

// Common thread-mapping setup
#define MM_PROLOG()                                                           \
    extern __shared__ char dsm[];                                             \
    const uint32_t sbase = smem_u32(dsm);                                     \
    const int tid  = threadIdx.x;                                             \
    const int lane = tid & 31;                                                \
    const int wid  = tid >> 5;                                                \
    const int wm   = wid & 1;                                                 \
    const int wn   = wid >> 1;                                                \
    const int g  = lane >> 3, lr = lane & 7;                                  \
    const int aRow  = (g & 1) * 8 + lr;                                       \
    const int aKoff = (g >> 1) * 16;                                          \
    const int bRow  = (g >> 1) * 8 + lr;                                      \
    const int bKoff = (g & 1) * 16;                                           \
    const uint32_t aOffW = (uint32_t)(wm * 64 + aRow) * (STR * 2) + aKoff;    \
    const uint32_t bOffW = (uint32_t)(wn * 32 + bRow) * (STR * 2) + bKoff;    \
    float acc[4][4][4];                                                       \
    _Pragma("unroll") for (int i = 0; i < 4; i++)                             \
    _Pragma("unroll") for (int j = 0; j < 4; j++)                             \
    _Pragma("unroll") for (int q = 0; q < 4; q++) acc[i][j][q] = 0.f;

// Q projection: 2-pass A, out fp16 hi/lo
__global__ __launch_bounds__(256) void mm_q(
    const __half* __restrict__ Ahi, const __half* __restrict__ Alo,
    const __half* __restrict__ BT, __half* __restrict__ Oh,
    __half* __restrict__ Ol, int M, int N, int K)
{
    MM_PROLOG();
    const int bm = blockIdx.y, bn = blockIdx.x;
    mm_core<2>(Ahi + (size_t)(bm * 128) * K, Alo + (size_t)(bm * 128) * K,
               BT + (size_t)(bn * 128) * K, K, sbase, tid, aOffW, bOffW, acc);

    const int tr = lane >> 2, tc = (lane & 3) * 2;
#pragma unroll
    for (int mi = 0; mi < 4; mi++)
#pragma unroll
        for (int nj = 0; nj < 4; nj++) {
            const int row = bm * 128 + wm * 64 + mi * 16 + tr;
            const int col = bn * 128 + wn * 32 + nj * 8 + tc;
#pragma unroll
            for (int hf = 0; hf < 2; hf++) {
                const int rr = row + hf * 8;
                float x0 = acc[mi][nj][hf * 2 + 0];
                float x1 = acc[mi][nj][hf * 2 + 1];
                __half h0 = __float2half_rn(x0), h1 = __float2half_rn(x1);
                __half l0 = __float2half_rn(x0 - __half2float(h0));
                __half l1 = __float2half_rn(x1 - __half2float(h1));
                __half2 vh; vh.x = h0; vh.y = h1;
                __half2 vl; vl.x = l0; vl.y = l1;
                *(__half2*)(Oh + (size_t)rr * N + col) = vh;
                *(__half2*)(Ol + (size_t)rr * N + col) = vl;
            }
        }
}

// Fused K+V projection: blockIdx.z = 0 -> K (single out), 1 -> V (hi/lo)
__global__ __launch_bounds__(256) void mm_kv(
    const __half* __restrict__ Ahi, const __half* __restrict__ Alo,
    const __half* __restrict__ BTk, const __half* __restrict__ BTv,
    __half* __restrict__ Ko, __half* __restrict__ Vh, __half* __restrict__ Vl,
    int M, int N, int K)
{
    MM_PROLOG();
    const int bm = blockIdx.y, bn = blockIdx.x, z = blockIdx.z;
    const __half* BT = z ? BTv : BTk;
    mm_core<2>(Ahi + (size_t)(bm * 128) * K, Alo + (size_t)(bm * 128) * K,
               BT + (size_t)(bn * 128) * K, K, sbase, tid, aOffW, bOffW, acc);

    const int tr = lane >> 2, tc = (lane & 3) * 2;
#pragma unroll
    for (int mi = 0; mi < 4; mi++)
#pragma unroll
        for (int nj = 0; nj < 4; nj++) {
            const int row = bm * 128 + wm * 64 + mi * 16 + tr;
            const int col = bn * 128 + wn * 32 + nj * 8 + tc;
#pragma unroll
            for (int hf = 0; hf < 2; hf++) {
                const int rr = row + hf * 8;
                float x0 = acc[mi][nj][hf * 2 + 0];
                float x1 = acc[mi][nj][hf * 2 + 1];
                __half h0 = __float2half_rn(x0), h1 = __float2half_rn(x1);
                __half2 vh; vh.x = h0; vh.y = h1;
                if (z == 0) {
                    *(__half2*)(Ko + (size_t)rr * N + col) = vh;
                } else {
                    __half l0 = __float2half_rn(x0 - __half2float(h0));
                    __half l1 = __float2half_rn(x1 - __half2float(h1));
                    __half2 vl; vl.x = l0; vl.y = l1;
                    *(__half2*)(Vh + (size_t)rr * N + col) = vh;
                    *(__half2*)(Vl + (size_t)rr * N + col) = vl;
                }
            }
        }
}

// O projection: 1-pass A, fp32 out + bias
__global__ __launch_bounds__(256) void mm_o(
    const __half* __restrict__ A, const __half* __restrict__ BT,
    const float* __restrict__ bias, float* __restrict__ C,
    int M, int N, int K)
{
    MM_PROLOG();
    const int bm = blockIdx.y, bn = blockIdx.x;
    mm_core<1>(A + (size_t)(bm * 128) * K, nullptr,
               BT + (size_t)(bn * 128) * K, K, sbase, tid, aOffW, bOffW, acc);

    const int tr = lane >> 2, tc = (lane & 3) * 2;
#pragma unroll
    for (int mi = 0; mi < 4; mi++)
#pragma unroll
        for (int nj = 0; nj < 4; nj++) {
            const int row = bm * 128 + wm * 64 + mi * 16 + tr;
            const int col = bn * 128 + wn * 32 + nj * 8 + tc;
            float b0 = bias[col], b1 = bias[col + 1];
#pragma unroll
            for (int hf = 0; hf < 2; hf++) {
                const int rr = row + hf * 8;
                float2 v = {acc[mi][nj][hf * 2 + 0] + b0,
                            acc[mi][nj][hf * 2 + 1] + b1};
                *(float2*)(C + (size_t)rr * N + col) = v;
            }
        }
}

// ---------------------------------------------------------------------------
// Tensor-core flash attention (unchanged compute; single-fp16 AO out)
// ---------------------------------------------------------------------------
constexpr int FP = 72;
constexpr int FQ_ELE = 128 * FP;
constexpr int FT_ELE = 64 * FP;
constexpr int FBUF_ELE = 3 * FT_ELE;
constexpr int FSMEM = (2 * FQ_ELE + 2 * FBUF_ELE) * 2;

__global__ __launch_bounds__(256) void flash_mma(
    const __half* __restrict__ Qh, const __half* __restrict__ Ql,
    const __half* __restrict__ Kh,
    const __half* __restrict__ Vh, const __half* __restrict__ Vl,
    __half* __restrict__ AO)
{
    extern __shared__ __half fsm[];
    __half* sQh = fsm;
    __half* sQl = sQh + FQ_ELE;
    __half* sBuf = sQl + FQ_ELE;

    const int tid  = threadIdx.x;
    const int lane = tid & 31;
    const int w    = tid >> 5;
    const int b  = blockIdx.y >> 4, h = blockIdx.y & 15;
    const size_t bq  = (size_t)b * SQ + blockIdx.x * 128;
    const size_t bkv = (size_t)b * SKV;
    const int hc = h * Dh;

    {
        const int r = tid >> 1, c8 = (tid & 1) * 4;
#pragma unroll
        for (int i = 0; i < 4; i++) {
            int cc = c8 + (i & 3);
            *(uint4*)(sQh + r * FP + cc * 8) =
                *(const uint4*)(Qh + (bq + r) * ID + hc + cc * 8);
            *(uint4*)(sQl + r * FP + cc * 8) =
                *(const uint4*)(Ql + (bq + r) * ID + hc + cc * 8);
        }
    }

    auto issue_tile = [&](int jt, int bi) {
        uint32_t kb  = smem_u32(sBuf + bi * FBUF_ELE);
        uint32_t vhb = kb + FT_ELE * 2;
        uint32_t vlb = vhb + FT_ELE * 2;
        const size_t grow = (bkv + jt * 64) * ID + hc;
#pragma unroll
        for (int i = 0; i < 2; i++) {
            int idx = tid + i * 256;
            int r = idx >> 3, c8 = idx & 7;
            uint32_t so = (uint32_t)(r * FP + c8 * 8) * 2;
            CP_ASYNC16(kb + so, Kh + grow + (size_t)r * ID + c8 * 8);
        }
#pragma unroll
        for (int i = 0; i < 2; i++) {
            int idx = tid + i * 256;
            int r = idx >> 3, c8 = idx & 7;
            uint32_t so = (uint32_t)(r * FP + c8 * 8) * 2;
            CP_ASYNC16(vhb + so, Vh + grow + (size_t)r * ID + c8 * 8);
            CP_ASYNC16(vlb + so, Vl + grow + (size_t)r * ID + c8 * 8);
        }
        CP_COMMIT();
    };

    issue_tile(0, 0);
    __syncthreads();

    const int g2 = lane >> 3, lr = lane & 7;
    const int aRow = (g2 & 1) * 8 + lr, aK = (g2 >> 1) * 16;
    uint32_t qhf[4][4], qlf[4][4];
    {
        uint32_t qhB = smem_u32(sQh) + (uint32_t)(w * 16 + aRow) * (FP * 2) + aK;
        uint32_t qlB = smem_u32(sQl) + (uint32_t)(w * 16 + aRow) * (FP * 2) + aK;
#pragma unroll
        for (int kd = 0; kd < 4; kd++) {
            LDSM4(qhf[kd], qhB + kd * 32);
            LDSM4(qlf[kd], qlB + kd * 32);
        }
    }

    const int bRow = (g2 >> 1) * 8 + lr, bK = (g2 & 1) * 16;
    const int vRow = (g2 & 1) * 8 + lr, vCol = (g2 >> 1) * 8;

    float o[8][4];
#pragma unroll
    for (int j = 0; j < 8; j++)
#pragma unroll
        for (int q = 0; q < 4; q++) o[j][q] = 0.f;
    float m0 = -1e30f, m1 = -1e30f, l0 = 0.f, l1 = 0.f;

    constexpr int NT = SKV / 64;
    for (int jt = 0; jt < NT; jt++) {
        if (jt + 1 < NT) issue_tile(jt + 1, (jt + 1) & 1);
        if (jt == NT - 1) asm volatile("cp.async.wait_group 0;" ::: "memory");
        else              asm volatile("cp.async.wait_group 1;" ::: "memory");
        __syncthreads();

        const int bi = jt & 1;
        const uint32_t kBase  = smem_u32(sBuf + bi * FBUF_ELE) + (uint32_t)bRow * (FP * 2) + bK;
        const uint32_t vhBase = smem_u32(sBuf + bi * FBUF_ELE + FT_ELE) + (uint32_t)vRow * (FP * 2) + vCol * 2;
        const uint32_t vlBase = vhBase + FT_ELE * 2;

        float s[8][4];
#pragma unroll
        for (int j = 0; j < 8; j++)
#pragma unroll
            for (int q = 0; q < 4; q++) s[j][q] = 0.f;

#pragma unroll
        for (int kd = 0; kd < 4; kd++) {
#pragma unroll
            for (int jn = 0; jn < 4; jn++) {
                uint32_t kf[4];
                LDSM4(kf, kBase + (uint32_t)(jn * 16) * (FP * 2) + kd * 32);
                MMA_F16(s[2 * jn + 0], qhf[kd], kf[0], kf[1]);
                MMA_F16(s[2 * jn + 1], qhf[kd], kf[2], kf[3]);
                MMA_F16(s[2 * jn + 0], qlf[kd], kf[0], kf[1]);
                MMA_F16(s[2 * jn + 1], qlf[kd], kf[2], kf[3]);
            }
        }

        float mx0 = -1e30f, mx1 = -1e30f;
#pragma unroll
        for (int j = 0; j < 8; j++) {
            s[j][0] *= ATT_SCALE; s[j][1] *= ATT_SCALE;
            s[j][2] *= ATT_SCALE; s[j][3] *= ATT_SCALE;
            mx0 = fmaxf(mx0, fmaxf(s[j][0], s[j][1]));
            mx1 = fmaxf(mx1, fmaxf(s[j][2], s[j][3]));
        }
        mx0 = fmaxf(mx0, __shfl_xor_sync(0xffffffffu, mx0, 1));
        mx0 = fmaxf(mx0, __shfl_xor_sync(0xffffffffu, mx0, 2));
        mx1 = fmaxf(mx1, __shfl_xor_sync(0xffffffffu, mx1, 1));
        mx1 = fmaxf(mx1, __shfl_xor_sync(0xffffffffu, mx1, 2));

        const float m0n = fmaxf(m0, mx0), m1n = fmaxf(m1, mx1);
        const float f0 = __expf(m0 - m0n), f1 = __expf(m1 - m1n);
        float sum0 = 0.f, sum1 = 0.f;
#pragma unroll
        for (int j = 0; j < 8; j++) {
            s[j][0] = __expf(s[j][0] - m0n); s[j][1] = __expf(s[j][1] - m0n);
            s[j][2] = __expf(s[j][2] - m1n); s[j][3] = __expf(s[j][3] - m1n);
            sum0 += s[j][0] + s[j][1];
            sum1 += s[j][2] + s[j][3];
        }
        sum0 += __shfl_xor_sync(0xffffffffu, sum0, 1);
        sum0 += __shfl_xor_sync(0xffffffffu, sum0, 2);
        sum1 += __shfl_xor_sync(0xffffffffu, sum1, 1);
        sum1 += __shfl_xor_sync(0xffffffffu, sum1, 2);
        l0 = l0 * f0 + sum0;
        l1 = l1 * f1 + sum1;
        m0 = m0n; m1 = m1n;

#pragma unroll
        for (int j = 0; j < 8; j++) {
            o[j][0] *= f0; o[j][1] *= f0;
            o[j][2] *= f1; o[j][3] *= f1;
        }

        uint32_t pf[4][4];
#pragma unroll
        for (int kd = 0; kd < 4; kd++) {
            pf[kd][0] = pack2h(s[2 * kd + 0][0], s[2 * kd + 0][1]);
            pf[kd][1] = pack2h(s[2 * kd + 0][2], s[2 * kd + 0][3]);
            pf[kd][2] = pack2h(s[2 * kd + 1][0], s[2 * kd + 1][1]);
            pf[kd][3] = pack2h(s[2 * kd + 1][2], s[2 * kd + 1][3]);
        }

#pragma unroll
        for (int kd = 0; kd < 4; kd++) {
#pragma unroll
            for (int jn = 0; jn < 4; jn++) {
                uint32_t vf[4];
                LDSM4T(vf, vhBase + (uint32_t)(kd * 16) * (FP * 2) + jn * 32);
                MMA_F16(o[2 * jn + 0], pf[kd], vf[0], vf[1]);
                MMA_F16(o[2 * jn + 1], pf[kd], vf[2], vf[3]);
                LDSM4T(vf, vlBase + (uint32_t)(kd * 16) * (FP * 2) + jn * 32);
                MMA_F16(o[2 * jn + 0], pf[kd], vf[0], vf[1]);
                MMA_F16(o[2 * jn + 1], pf[kd], vf[2], vf[3]);
            }
        }
        __syncthreads();
    }

    const float inv0 = 1.f / l0, inv1 = 1.f / l1;
    const int rg = lane >> 2, tc = (lane & 3) * 2;
#pragma unroll
    for (int j = 0; j < 8; j++) {
        const int col = hc + j * 8 + tc;
#pragma unroll
        for (int hf = 0; hf < 2; hf++) {
            const size_t row = bq + w * 16 + rg + hf * 8;
            float x0 = o[j][hf * 2 + 0] * (hf ? inv1 : inv0);
            float x1 = o[j][hf * 2 + 1] * (hf ? inv1 : inv0);
            __half2 vh; vh.x = __float2half_rn(x0); vh.y = __float2half_rn(x1);
            *(__half2*)(AO + row * ID + col) = vh;
        }
    }
}

// ---------------------------------------------------------------------------
// Launch  (order chosen so launch #5 = mm_q for ncu -s 5 -c 1)
// ---------------------------------------------------------------------------
extern "C" void kernel_launch(void* const* d_in, const int* in_sizes, int n_in,
                              void* d_out, int out_size)
{
    const float* x   = (const float*)d_in[0];
    const float* ctx = (const float*)d_in[1];
    const float* Wq  = (const float*)d_in[2];
    const float* Wk  = (const float*)d_in[3];
    const float* Wv  = (const float*)d_in[4];
    const float* Wo  = (const float*)d_in[5];
    const float* bo  = (const float*)d_in[6];
    float* out = (float*)d_out;

    __half *qh, *ql, *kh, *vh, *vl, *ao, *xh, *xl, *ch, *cl;
    __half *wq, *wk, *wv, *wo;
    cudaGetSymbolAddress((void**)&qh, g_qh); cudaGetSymbolAddress((void**)&ql, g_ql);
    cudaGetSymbolAddress((void**)&kh, g_kh);
    cudaGetSymbolAddress((void**)&vh, g_vh); cudaGetSymbolAddress((void**)&vl, g_vl);
    cudaGetSymbolAddress((void**)&ao, g_ao);
    cudaGetSymbolAddress((void**)&xh, g_xh); cudaGetSymbolAddress((void**)&xl, g_xl);
    cudaGetSymbolAddress((void**)&ch, g_ch); cudaGetSymbolAddress((void**)&cl, g_cl);
    cudaGetSymbolAddress((void**)&wq, g_wq); cudaGetSymbolAddress((void**)&wk, g_wk);
    cudaGetSymbolAddress((void**)&wv, g_wv); cudaGetSymbolAddress((void**)&wo, g_wo);

    cudaFuncSetAttribute(flash_mma, cudaFuncAttributeMaxDynamicSharedMemorySize, FSMEM);
    cudaFuncSetAttribute(mm_q,  cudaFuncAttributeMaxDynamicSharedMemorySize, MMSMEM);
    cudaFuncSetAttribute(mm_kv, cudaFuncAttributeMaxDynamicSharedMemorySize, MMSMEM);
    cudaFuncSetAttribute(mm_o,  cudaFuncAttributeMaxDynamicSharedMemorySize, MMSMEM);

    // 0..4: conversions needed before mm_q / mm_kv
    splitk<<<(int)(NX  / 4 / 256), 256>>>(x,   xh, xl, (int)(NX  / 4));      // 0
    tsp_h<<<dim3(ID / 32, QD / 32), dim3(32, 8)>>>(Wq, wq, QD, ID);          // 1
    splitk<<<(int)(NCX / 4 / 256), 256>>>(ctx, ch, cl, (int)(NCX / 4));      // 2
    tsp_h<<<dim3(ID / 32, CD / 32), dim3(32, 8)>>>(Wk, wk, CD, ID);          // 3
    tsp_h<<<dim3(ID / 32, CD / 32), dim3(32, 8)>>>(Wv, wv, CD, ID);          // 4

    // 5: Q projection (ncu target)
    mm_q<<<dim3(ID / 128, (Bz * SQ) / 128), 256, MMSMEM>>>(
        xh, xl, wq, qh, ql, Bz * SQ, ID, QD);

    // 6: fused K+V projections
    mm_kv<<<dim3(ID / 128, (Bz * SKV) / 128, 2), 256, MMSMEM>>>(
        ch, cl, wk, wv, kh, vh, vl, Bz * SKV, ID, CD);

    // 7: attention
    flash_mma<<<dim3(SQ / 128, Bz * H), 256, FSMEM>>>(qh, ql, kh, vh, vl, ao);

    // 8: Wo transpose; 9: O projection (single-pass A)
    tsp_h<<<dim3(QD / 32, ID / 32), dim3(32, 8)>>>(Wo, wo, ID, QD);
    mm_o<<<dim3(QD / 128, (Bz * SQ) / 128), 256, MMSMEM>>>(
        ao, wo, bo, out, Bz * SQ, QD, ID);
}